// round 12
// baseline (speedup 1.0000x reference)
#include <cuda_runtime.h>

#define NB 8
#define NC 512
#define NL 1024
#define NH 8
#define ND 64

typedef unsigned long long u64;
typedef unsigned int u32;

// ---------------- scratch (allocation-free rule) ---------------------------
// Q/K: tf32 packed [bh][row][k(8)][q4(4)] float4 {hi(d0), hi(d0+4), lo(d0), lo(d0+4)},
// d0 = 8k + q4.
__device__ float4 g_q4[NB*NH*NL*32];
__device__ float4 g_k4[NB*NH*NL*32];
// V: tf32 hi only, [bh][d][gp(128)][j(4)] float2 {v(d, 8gp+j), v(d, 8gp+j+4)}
__device__ float2 g_v2 [NB*NH*64*512];
__device__ float  g_o  [NB*NL*NC];     // attention output, [b][l][c]
// weights pre-packed: [cv][g][t*64+c][36] f2 pairs over i {w(8k+q4), w(8k+q4+4)}
__device__ float2 g_wp_h[3*64*192*36];
__device__ float2 g_wp_l[3*64*192*36];

// ---------------- tensor helpers (legacy mma.sync on sm_103) ---------------
__device__ __forceinline__ float tf32hi(float x) {
    u32 r; asm("cvt.rna.tf32.f32 %0, %1;" : "=r"(r) : "f"(x));
    return __uint_as_float(r);
}
__device__ __forceinline__ void mma8(float d[4], const u32 a[4], u32 b0, u32 b1) {
    asm volatile("mma.sync.aligned.m16n8k8.row.col.f32.tf32.tf32.f32 "
        "{%0,%1,%2,%3}, {%4,%5,%6,%7}, {%8,%9}, {%0,%1,%2,%3};"
        : "+f"(d[0]), "+f"(d[1]), "+f"(d[2]), "+f"(d[3])
        : "r"(a[0]), "r"(a[1]), "r"(a[2]), "r"(a[3]), "r"(b0), "r"(b1));
}
__device__ __forceinline__ u32 smem_u32(const void* p) {
    u32 a; asm("{ .reg .u64 t; cvta.to.shared.u64 t, %1; cvt.u32.u64 %0, t; }"
               : "=r"(a) : "l"(p)); return a;
}

// ---------------------------------------------------------------------------
// pack_w: weights -> pair-packed tf32 hi/lo, [cv][g][t*64+c][36] f2.
// Q weights (cv=0) pre-scaled by 1/sqrt(8). grid (64, 3) x 256 threads.
// ---------------------------------------------------------------------------
__global__ void pack_w(const float* __restrict__ wq, const float* __restrict__ wk,
                       const float* __restrict__ wv)
{
    int g  = blockIdx.x;
    int cv = blockIdx.y;
    const float* w = (cv == 0) ? wq : (cv == 1) ? wk : wv;
    float s = (cv == 0) ? 0.35355339059327373f : 1.0f;

    int tid = threadIdx.x;
    #pragma unroll
    for (int it = 0; it < 24; ++it) {
        int u  = it*256 + tid;            // < 6144
        int r  = u >> 5;                  // t*64 + c
        int k4 = u & 31;
        int t  = r >> 6, c = r & 63;
        int i0 = ((k4 >> 2) << 3) | (k4 & 3);
        float v0 = w[(size_t)((g*64 + c)*64 + i0    )*3 + t] * s;
        float v1 = w[(size_t)((g*64 + c)*64 + i0 + 4)*3 + t] * s;
        float h0 = tf32hi(v0), h1 = tf32hi(v1);
        size_t base = (size_t)((cv*64 + g)*192 + r)*36 + k4;
        g_wp_h[base] = make_float2(h0, h1);
        g_wp_l[base] = make_float2(v0 - h0, v1 - h1);
    }
}

// ---------------------------------------------------------------------------
// conv_mma: grouped conv1d as tensor-core GEMM.
// cv=0: Q conv (x3) -> g_q4.  cv=1: K conv (x3) -> g_k4 AND V conv (x2) -> g_v2,
// sharing one x-stage + transpose (both use kin).
// grid (8 ltiles, 64 bg, 2), 256 thr = 8 warps.
// ---------------------------------------------------------------------------
#define OFF_RAW 0                           // xs [64 i][134 f]   = 34,304 B
#define OFF_XH  34304                       // xp_hi [132][36] f2 = 38,016 B
#define OFF_XL  (OFF_XH + 38016)
#define OFF_WH  (OFF_XL + 38016)            // wp_hi [192][36] f2 = 55,296 B
#define OFF_WL  (OFF_WH + 55296)
#define SMEM_CONV (OFF_WL + 55296)          // 220,928 B

__global__ __launch_bounds__(256)
void conv_mma(const float* __restrict__ qin, const float* __restrict__ kin)
{
    extern __shared__ __align__(16) char sm[];
    u32 smb = smem_u32(sm);
    float*  xs = (float*) (sm + OFF_RAW);
    float*  oT = (float*) (sm + OFF_RAW);   // reused after GEMM
    float2* XH = (float2*)(sm + OFF_XH);
    float2* XL = (float2*)(sm + OFF_XL);
    float2* WH = (float2*)(sm + OFF_WH);
    float2* WL = (float2*)(sm + OFF_WL);

    int tid  = threadIdx.x;
    int w    = tid >> 5;
    int lane = tid & 31;
    int g    = lane >> 2;
    int q4   = lane & 3;
    int lt   = blockIdx.x * 128;
    int bg   = blockIdx.y;
    int cv   = blockIdx.z;                  // 0=Q, 1=K+V fused
    int b    = bg >> 3, gr = bg & 7;

    const float* xg = ((cv == 0) ? qin : kin) + (size_t)(b*NC + gr*64) * NL;
    int wcv = (cv == 0) ? 0 : 1;

    // ---- cp.async weights (hi+lo for Q or K) ----
    {
        const char* wsh = (const char*)g_wp_h + (size_t)(wcv*64 + gr)*192*288;
        const char* wsl = (const char*)g_wp_l + (size_t)(wcv*64 + gr)*192*288;
        #pragma unroll
        for (int it = 0; it < 14; ++it) {
            int u = it*256 + tid;
            if (u < 3456) {
                asm volatile("cp.async.cg.shared.global [%0], [%1], 16;"
                             :: "r"(smb + OFF_WH + u*16), "l"(wsh + (size_t)u*16) : "memory");
                asm volatile("cp.async.cg.shared.global [%0], [%1], 16;"
                             :: "r"(smb + OFF_WL + u*16), "l"(wsl + (size_t)u*16) : "memory");
            }
        }
        asm volatile("cp.async.commit_group;" ::: "memory");
    }

    // ---- stage raw x tile [64 i][132 r] (reflect pad), coalesced ----
    #pragma unroll
    for (int it = 0; it < 32; ++it) {
        int u = it*256 + tid;
        int i = u >> 7, r = u & 127;
        int l = lt - 1 + r;
        l = (l < 0) ? 1 : ((l >= NL) ? (2*NL - 2 - l) : l);
        xs[i*134 + r] = xg[(size_t)i*NL + l];
    }
    {   // tail rows 128..131
        int i = tid >> 2, r = 128 + (tid & 3);
        int l = lt - 1 + r;
        l = (l < 0) ? 1 : ((l >= NL) ? (2*NL - 2 - l) : l);
        xs[i*134 + r] = xg[(size_t)i*NL + l];
    }
    __syncthreads();

    // ---- transpose + tf32 split: fs = 8k + 2q + h, i = 8k + q + 4h ----
    #pragma unroll
    for (int it = 0; it < 33; ++it) {
        int u = it*256 + tid;             // < 8448 = 132*64
        int r = u >> 6, fs = u & 63;
        int k = fs >> 3, q = (fs >> 1) & 3, h = fs & 1;
        int i = 8*k + q + 4*h;
        float v = xs[i*134 + r];
        float hv = tf32hi(v);
        ((float*)XH)[r*72 + fs] = hv;
        ((float*)XL)[r*72 + fs] = v - hv;
    }
    asm volatile("cp.async.wait_group 0;" ::: "memory");
    __syncthreads();

    int base = w*16 + g;
    float oacc[8][4];

    // ================= pass A: Q or K, x3-compensated =================
    #pragma unroll
    for (int n = 0; n < 8; ++n)
        #pragma unroll
        for (int e = 0; e < 4; ++e) oacc[n][e] = 0.f;

    #pragma unroll
    for (int t = 0; t < 3; ++t) {
        #pragma unroll
        for (int k = 0; k < 8; ++k) {
            float2 ah0 = XH[(base + t    )*36 + k*4 + q4];
            float2 ah1 = XH[(base + t + 8)*36 + k*4 + q4];
            float2 al0 = XL[(base + t    )*36 + k*4 + q4];
            float2 al1 = XL[(base + t + 8)*36 + k*4 + q4];
            u32 ahi[4] = {__float_as_uint(ah0.x), __float_as_uint(ah1.x),
                          __float_as_uint(ah0.y), __float_as_uint(ah1.y)};
            u32 alo[4] = {__float_as_uint(al0.x), __float_as_uint(al1.x),
                          __float_as_uint(al0.y), __float_as_uint(al1.y)};
            #pragma unroll
            for (int n = 0; n < 8; ++n) {
                int ro = (t*64 + 8*n + g)*36 + k*4 + q4;
                float2 bh = WH[ro];
                float2 bl = WL[ro];
                mma8(oacc[n], ahi, __float_as_uint(bh.x), __float_as_uint(bh.y));
                mma8(oacc[n], alo, __float_as_uint(bh.x), __float_as_uint(bh.y));
                mma8(oacc[n], ahi, __float_as_uint(bl.x), __float_as_uint(bl.y));
            }
        }
    }

    // store accumulators to oT[c][134 + l]
    {
        int l0 = base, l1 = base + 8;
        #pragma unroll
        for (int n = 0; n < 8; ++n) {
            int c0 = 8*n + 2*q4;
            oT[(c0    )*134 + l0] = oacc[n][0];
            oT[(c0 + 1)*134 + l0] = oacc[n][1];
            oT[(c0    )*134 + l1] = oacc[n][2];
            oT[(c0 + 1)*134 + l1] = oacc[n][3];
        }
    }
    __syncthreads();

    // for fused block: WL is dead now — prefetch V weights (hi) into it
    if (cv == 1) {
        const char* wsv = (const char*)g_wp_h + (size_t)(2*64 + gr)*192*288;
        #pragma unroll
        for (int it = 0; it < 14; ++it) {
            int u = it*256 + tid;
            if (u < 3456)
                asm volatile("cp.async.cg.shared.global [%0], [%1], 16;"
                             :: "r"(smb + OFF_WL + u*16), "l"(wsv + (size_t)u*16) : "memory");
        }
        asm volatile("cp.async.commit_group;" ::: "memory");
    }

    // epilogue A: packed float4 {h0, h1, l0, l1} -> g_q4 / g_k4
    {
        float4* dst = ((cv == 0) ? g_q4 : g_k4) + (size_t)bg*NL*32;
        #pragma unroll
        for (int it = 0; it < 16; ++it) {
            int u  = it*256 + tid;        // < 4096
            int l  = u >> 5, kq = u & 31;
            int d0 = ((kq >> 2) << 3) | (kq & 3);
            float f0 = oT[(d0    )*134 + l];
            float f1 = oT[(d0 + 4)*134 + l];
            float h0 = tf32hi(f0), h1 = tf32hi(f1);
            dst[(size_t)(lt + l)*32 + kq] = make_float4(h0, h1, f0 - h0, f1 - h1);
        }
    }

    if (cv != 1) return;

    // ================= pass B: V conv, x2 (x split, w hi) =================
    asm volatile("cp.async.wait_group 0;" ::: "memory");
    __syncthreads();                       // epilogue-A reads of oT done

    #pragma unroll
    for (int n = 0; n < 8; ++n)
        #pragma unroll
        for (int e = 0; e < 4; ++e) oacc[n][e] = 0.f;

    #pragma unroll
    for (int t = 0; t < 3; ++t) {
        #pragma unroll
        for (int k = 0; k < 8; ++k) {
            float2 ah0 = XH[(base + t    )*36 + k*4 + q4];
            float2 ah1 = XH[(base + t + 8)*36 + k*4 + q4];
            float2 al0 = XL[(base + t    )*36 + k*4 + q4];
            float2 al1 = XL[(base + t + 8)*36 + k*4 + q4];
            u32 ahi[4] = {__float_as_uint(ah0.x), __float_as_uint(ah1.x),
                          __float_as_uint(ah0.y), __float_as_uint(ah1.y)};
            u32 alo[4] = {__float_as_uint(al0.x), __float_as_uint(al1.x),
                          __float_as_uint(al0.y), __float_as_uint(al1.y)};
            #pragma unroll
            for (int n = 0; n < 8; ++n) {
                float2 bh = WL[(t*64 + 8*n + g)*36 + k*4 + q4];   // V weights (hi)
                mma8(oacc[n], ahi, __float_as_uint(bh.x), __float_as_uint(bh.y));
                mma8(oacc[n], alo, __float_as_uint(bh.x), __float_as_uint(bh.y));
            }
        }
    }

    {
        int l0 = base, l1 = base + 8;
        #pragma unroll
        for (int n = 0; n < 8; ++n) {
            int c0 = 8*n + 2*q4;
            oT[(c0    )*134 + l0] = oacc[n][0];
            oT[(c0 + 1)*134 + l0] = oacc[n][1];
            oT[(c0    )*134 + l1] = oacc[n][2];
            oT[(c0 + 1)*134 + l1] = oacc[n][3];
        }
    }
    __syncthreads();

    // epilogue V (R9/R11 layout, unchanged)
    {
        float2* vh = g_v2 + (size_t)bg*64*512;
        #pragma unroll
        for (int it = 0; it < 16; ++it) {
            int u  = it*256 + tid;        // < 4096
            int c  = u >> 6;
            int gp = (u >> 2) & 15, j = u & 3;
            float v0 = oT[c*134 + gp*8 + j];
            float v1 = oT[c*134 + gp*8 + j + 4];
            vh[(size_t)c*512 + ((lt >> 3) + gp)*4 + j] =
                make_float2(tf32hi(v0), tf32hi(v1));
        }
    }
}

// ---------------------------------------------------------------------------
// Causal attention: mma.sync tf32, QK x3 / PV x2. K packed float4 -> one
// LDS.128 per B-fragment; cp.async double-buffered staging. (R11 math.)
// ---------------------------------------------------------------------------
#define KPIT4 36                       // float4 pitch per packed K smem row
#define KSTG_BYTES (64*KPIT4*16)       // 36,864
#define VPIT2 36
#define VSTG_BYTES (64*VPIT2*8)        // 18,432
#define STAGE_BYTES (KSTG_BYTES + VSTG_BYTES)   // 55,296
#define SMEM_ATTN (2*STAGE_BYTES)               // 110,592

__global__ __launch_bounds__(256)
void attn_kernel()
{
    extern __shared__ __align__(16) char smraw[];
    u32 smb = smem_u32(smraw);

    int tid  = threadIdx.x;
    int w    = tid >> 5;
    int lane = tid & 31;
    int g    = lane >> 2;
    int q4   = lane & 3;
    int bh   = blockIdx.y;
    int qt   = 7 - blockIdx.x;
    int row0 = qt * 128;

    // ---- Q fragments from packed g_q4 (1 LDG.128 per row per k) ----
    const float4* qp = g_q4 + (size_t)bh*NL*32;
    int rbl = w*16 + g;
    u32 qAhi[8][4], qAlo[8][4];
    #pragma unroll
    for (int k = 0; k < 8; ++k) {
        float4 f0 = qp[(size_t)(row0+rbl  )*32 + k*4 + q4];
        float4 f1 = qp[(size_t)(row0+rbl+8)*32 + k*4 + q4];
        qAhi[k][0] = __float_as_uint(f0.x);
        qAhi[k][1] = __float_as_uint(f1.x);
        qAhi[k][2] = __float_as_uint(f0.y);
        qAhi[k][3] = __float_as_uint(f1.y);
        qAlo[k][0] = __float_as_uint(f0.z);
        qAlo[k][1] = __float_as_uint(f1.z);
        qAlo[k][2] = __float_as_uint(f0.w);
        qAlo[k][3] = __float_as_uint(f1.w);
    }

    float oacc[8][4];
    #pragma unroll
    for (int n = 0; n < 8; ++n)
        #pragma unroll
        for (int e = 0; e < 4; ++e) oacc[n][e] = 0.f;
    float s0 = 0.f, s1 = 0.f;

    int rbase = row0 + rbl;
    int nkt   = 2*qt + 2;
    int src0  = (lane & ~3) | (q4 >> 1);
    int src1  = src0 + 2;

    const char* k4g = (const char*)(g_k4 + (size_t)bh*NL*32);
    const char* vhg = (const char*)(g_v2 + (size_t)bh*64*512);

    auto stage = [&](int kt, int buf) {
        u32 base = smb + buf*STAGE_BYTES;
        #pragma unroll
        for (int i = 0; i < 12; ++i) {
            int u = i*256 + tid;                    // < 3072
            u32 dst; const char* src;
            if (u < 2048) {                         // K: 64 rows x 512B
                int r = u >> 5, c16 = u & 31;
                dst = base + r*(KPIT4*16) + c16*16;
                src = k4g + ((size_t)(kt*64 + r)*32)*16 + c16*16;
            } else {                                // V: 64 rows x 256B
                int v = u - 2048;
                int r = v >> 4, c16 = v & 15;
                dst = base + KSTG_BYTES + r*(VPIT2*8) + c16*16;
                src = vhg + ((size_t)r*512 + kt*32)*8 + c16*16;
            }
            asm volatile("cp.async.cg.shared.global [%0], [%1], 16;"
                         :: "r"(dst), "l"(src) : "memory");
        }
        asm volatile("cp.async.commit_group;" ::: "memory");
    };

    stage(0, 0);

    for (int kt = 0; kt < nkt; ++kt) {
        int buf = kt & 1;
        __syncthreads();
        if (kt + 1 < nkt) {
            stage(kt + 1, (kt + 1) & 1);
            asm volatile("cp.async.wait_group 1;" ::: "memory");
        } else {
            asm volatile("cp.async.wait_group 0;" ::: "memory");
        }
        __syncthreads();

        const float4* K4 = (const float4*)(smraw + buf*STAGE_BYTES);
        const float2* Vh = (const float2*)(smraw + buf*STAGE_BYTES + KSTG_BYTES);

        // ---- S = Q K^T (x3): B frag = ONE LDS.128 ----
        float sc[8][4];
        #pragma unroll
        for (int n = 0; n < 8; ++n)
            #pragma unroll
            for (int e = 0; e < 4; ++e) sc[n][e] = 0.f;

        #pragma unroll
        for (int k = 0; k < 8; ++k) {
            #pragma unroll
            for (int n = 0; n < 8; ++n) {
                float4 kf = K4[(8*n + g)*KPIT4 + k*4 + q4];
                u32 bh0 = __float_as_uint(kf.x), bh1 = __float_as_uint(kf.y);
                mma8(sc[n], qAhi[k], bh0, bh1);
                mma8(sc[n], qAlo[k], bh0, bh1);
                mma8(sc[n], qAhi[k],
                     __float_as_uint(kf.z), __float_as_uint(kf.w));
            }
        }

        // ---- softmax: exp-direct + causal mask ----
        #pragma unroll
        for (int n = 0; n < 8; ++n) {
            int cbase = kt*64 + 8*n + 2*q4;
            #pragma unroll
            for (int e = 0; e < 4; ++e) {
                int r = rbase + ((e >> 1) << 3);
                int c = cbase + (e & 1);
                float p = (c > r) ? 0.f : __expf(sc[n][e]);
                sc[n][e] = p;
                if (e < 2) s0 += p; else s1 += p;
            }
        }

        // ---- O += P V^T (x2); P acc->A frag via quad shuffles ----
        #pragma unroll
        for (int kk = 0; kk < 8; ++kk) {
            float v00 = __shfl_sync(0xffffffffu, sc[kk][0], src0);
            float v01 = __shfl_sync(0xffffffffu, sc[kk][1], src0);
            float v20 = __shfl_sync(0xffffffffu, sc[kk][2], src0);
            float v21 = __shfl_sync(0xffffffffu, sc[kk][3], src0);
            float w00 = __shfl_sync(0xffffffffu, sc[kk][0], src1);
            float w01 = __shfl_sync(0xffffffffu, sc[kk][1], src1);
            float w20 = __shfl_sync(0xffffffffu, sc[kk][2], src1);
            float w21 = __shfl_sync(0xffffffffu, sc[kk][3], src1);
            bool odd = (q4 & 1);
            float a[4];
            a[0] = odd ? v01 : v00;
            a[1] = odd ? v21 : v20;
            a[2] = odd ? w01 : w00;
            a[3] = odd ? w21 : w20;
            u32 pahi[4], palo[4];
            #pragma unroll
            for (int e = 0; e < 4; ++e) {
                float h = tf32hi(a[e]);
                pahi[e] = __float_as_uint(h);
                palo[e] = __float_as_uint(a[e] - h);
            }
            #pragma unroll
            for (int n = 0; n < 8; ++n) {
                float2 bv = Vh[(8*n + g)*VPIT2 + kk*4 + q4];
                u32 b0 = __float_as_uint(bv.x), b1 = __float_as_uint(bv.y);
                mma8(oacc[n], pahi, b0, b1);
                mma8(oacc[n], palo, b0, b1);
            }
        }
    }

    s0 += __shfl_xor_sync(0xffffffffu, s0, 1);
    s0 += __shfl_xor_sync(0xffffffffu, s0, 2);
    s1 += __shfl_xor_sync(0xffffffffu, s1, 1);
    s1 += __shfl_xor_sync(0xffffffffu, s1, 2);
    float inv0 = 1.f / s0, inv1 = 1.f / s1;

    int b = bh >> 3, h = bh & 7;
    float* Ob0 = g_o + ((size_t)(b*NL + rbase    ))*NC + h*ND;
    float* Ob1 = g_o + ((size_t)(b*NL + rbase + 8))*NC + h*ND;
    #pragma unroll
    for (int n = 0; n < 8; ++n) {
        int d = 8*n + 2*q4;
        *(float2*)(Ob0 + d) = make_float2(oacc[n][0]*inv0, oacc[n][1]*inv0);
        *(float2*)(Ob1 + d) = make_float2(oacc[n][2]*inv1, oacc[n][3]*inv1);
    }
}

// ---------------------------------------------------------------------------
// Residual add + LayerNorm over channel, transposed-tile version (unchanged).
// ---------------------------------------------------------------------------
#define TL 16
__global__ __launch_bounds__(128)
void ln_kernel(const float* __restrict__ init, const float* __restrict__ gamma,
               const float* __restrict__ beta, float* __restrict__ y)
{
    __shared__ float xt[TL][NC + 4];

    int blk = blockIdx.x;
    int b   = blk >> 6;
    int lt  = (blk & 63) * TL;
    int tid = threadIdx.x;

    const float* ib = init + (size_t)b * NC * NL + lt;
    float*       yb = y    + (size_t)b * NC * NL + lt;

    for (int i = tid; i < NC * (TL/4); i += 128) {
        int c = i >> 2, j = i & 3;
        float4 v = *(const float4*)(ib + (size_t)c * NL + 4*j);
        xt[4*j+0][c] = v.x; xt[4*j+1][c] = v.y;
        xt[4*j+2][c] = v.z; xt[4*j+3][c] = v.w;
    }
    __syncthreads();

    int w = tid >> 5, lane = tid & 31;
    const float* ob_base = g_o + ((size_t)(b*NL + lt)) * NC;
    for (int r = w; r < TL; r += 4) {
        const float4* orow = (const float4*)(ob_base + (size_t)r * NC);
        float4 xv[4];
        float s1 = 0.f, s2 = 0.f;
        #pragma unroll
        for (int kk = 0; kk < 4; ++kk) {
            int c4 = lane + 32*kk;
            float4 ov = orow[c4];
            float4 iv = *(const float4*)(&xt[r][4*c4]);
            xv[kk] = make_float4(ov.x+iv.x, ov.y+iv.y, ov.z+iv.z, ov.w+iv.w);
            s1 += xv[kk].x + xv[kk].y + xv[kk].z + xv[kk].w;
            s2 += xv[kk].x*xv[kk].x + xv[kk].y*xv[kk].y
                + xv[kk].z*xv[kk].z + xv[kk].w*xv[kk].w;
        }
        #pragma unroll
        for (int off = 16; off; off >>= 1) {
            s1 += __shfl_xor_sync(0xffffffffu, s1, off);
            s2 += __shfl_xor_sync(0xffffffffu, s2, off);
        }
        float mu   = s1 * (1.f/512.f);
        float var  = s2 * (1.f/512.f) - mu*mu;
        float rstd = rsqrtf(var + 1e-5f);

        #pragma unroll
        for (int kk = 0; kk < 4; ++kk) {
            int c4 = lane + 32*kk;
            float4 gv = ((const float4*)gamma)[c4];
            float4 bv = ((const float4*)beta)[c4];
            float4 r4;
            r4.x = (xv[kk].x - mu)*rstd*gv.x + bv.x;
            r4.y = (xv[kk].y - mu)*rstd*gv.y + bv.y;
            r4.z = (xv[kk].z - mu)*rstd*gv.z + bv.z;
            r4.w = (xv[kk].w - mu)*rstd*gv.w + bv.w;
            *(float4*)(&xt[r][4*c4]) = r4;
        }
    }
    __syncthreads();

    for (int i = tid; i < NC * (TL/4); i += 128) {
        int c = i >> 2, j = i & 3;
        float4 v = make_float4(xt[4*j+0][c], xt[4*j+1][c],
                               xt[4*j+2][c], xt[4*j+3][c]);
        *(float4*)(yb + (size_t)c * NL + 4*j) = v;
    }
}

// ---------------------------------------------------------------------------
extern "C" void kernel_launch(void* const* d_in, const int* in_sizes, int n_in,
                              void* d_out, int out_size)
{
    const float* q     = (const float*)d_in[0];
    const float* k     = (const float*)d_in[1];
    // d_in[2] = mask — causal, handled analytically
    const float* wq    = (const float*)d_in[3];
    const float* wk    = (const float*)d_in[4];
    const float* wv    = (const float*)d_in[5];
    const float* gamma = (const float*)d_in[6];
    const float* beta  = (const float*)d_in[7];
    float* out = (float*)d_out;

    cudaFuncSetAttribute(conv_mma,
                         cudaFuncAttributeMaxDynamicSharedMemorySize, SMEM_CONV);
    cudaFuncSetAttribute(attn_kernel,
                         cudaFuncAttributeMaxDynamicSharedMemorySize, SMEM_ATTN);

    pack_w<<<dim3(64, 3), 256>>>(wq, wk, wv);
    conv_mma<<<dim3(8, 64, 2), 256, SMEM_CONV>>>(q, k);
    attn_kernel<<<dim3(8, NB*NH), 256, SMEM_ATTN>>>();
    ln_kernel<<<NB * (NL/TL), 128>>>(q, gamma, beta, out);
}

// round 13
// speedup vs baseline: 1.4165x; 1.4165x over previous
#include <cuda_runtime.h>

#define NB 8
#define NC 512
#define NL 1024
#define NH 8
#define ND 64

typedef unsigned long long u64;
typedef unsigned int u32;

// ---------------- scratch (allocation-free rule) ---------------------------
// Q/K: tf32 packed [bh][row][k(8)][q4(4)] float4 {hi(d0), hi(d0+4), lo(d0), lo(d0+4)},
// d0 = 8k + q4.
__device__ float4 g_q4[NB*NH*NL*32];
__device__ float4 g_k4[NB*NH*NL*32];
// V: tf32 hi only, [bh][d][gp(128)][j(4)] float2 {v(d, 8gp+j), v(d, 8gp+j+4)}
__device__ float2 g_v2 [NB*NH*64*512];
__device__ float  g_o  [NB*NL*NC];     // attention output, [b][l][c]
// weights pre-packed: [cv][g][t*64+c][36] f2 pairs over i {w(8k+q4), w(8k+q4+4)}
__device__ float2 g_wp_h[3*64*192*36];
__device__ float2 g_wp_l[3*64*192*36];

// ---------------- tensor helpers (legacy mma.sync on sm_103) ---------------
__device__ __forceinline__ float tf32hi(float x) {
    u32 r; asm("cvt.rna.tf32.f32 %0, %1;" : "=r"(r) : "f"(x));
    return __uint_as_float(r);
}
__device__ __forceinline__ void mma8(float d[4], const u32 a[4], u32 b0, u32 b1) {
    asm volatile("mma.sync.aligned.m16n8k8.row.col.f32.tf32.tf32.f32 "
        "{%0,%1,%2,%3}, {%4,%5,%6,%7}, {%8,%9}, {%0,%1,%2,%3};"
        : "+f"(d[0]), "+f"(d[1]), "+f"(d[2]), "+f"(d[3])
        : "r"(a[0]), "r"(a[1]), "r"(a[2]), "r"(a[3]), "r"(b0), "r"(b1));
}
__device__ __forceinline__ u32 smem_u32(const void* p) {
    u32 a; asm("{ .reg .u64 t; cvta.to.shared.u64 t, %1; cvt.u32.u64 %0, t; }"
               : "=r"(a) : "l"(p)); return a;
}

// ---------------------------------------------------------------------------
// pack_w: weights -> pair-packed tf32 hi/lo, [cv][g][t*64+c][36] f2.
// Q weights (cv=0) pre-scaled by 1/sqrt(8). grid (64, 3) x 256 threads.
// ---------------------------------------------------------------------------
__global__ void pack_w(const float* __restrict__ wq, const float* __restrict__ wk,
                       const float* __restrict__ wv)
{
    int g  = blockIdx.x;
    int cv = blockIdx.y;
    const float* w = (cv == 0) ? wq : (cv == 1) ? wk : wv;
    float s = (cv == 0) ? 0.35355339059327373f : 1.0f;

    int tid = threadIdx.x;
    #pragma unroll
    for (int it = 0; it < 24; ++it) {
        int u  = it*256 + tid;            // < 6144
        int r  = u >> 5;                  // t*64 + c
        int k4 = u & 31;
        int t  = r >> 6, c = r & 63;
        int i0 = ((k4 >> 2) << 3) | (k4 & 3);
        float v0 = w[(size_t)((g*64 + c)*64 + i0    )*3 + t] * s;
        float v1 = w[(size_t)((g*64 + c)*64 + i0 + 4)*3 + t] * s;
        float h0 = tf32hi(v0), h1 = tf32hi(v1);
        size_t base = (size_t)((cv*64 + g)*192 + r)*36 + k4;
        g_wp_h[base] = make_float2(h0, h1);
        g_wp_l[base] = make_float2(v0 - h0, v1 - h1);
    }
}

// ---------------------------------------------------------------------------
// conv_mma (R11 structure, uniform grid): grouped conv1d as tensor GEMM.
// M=128(l) x N=64(c) x K=192; mma m16n8k8 tf32.
// cv=0(Q),1(K): x3-compensated -> float4-packed g_q4/g_k4.
// cv=2(V): x2 (w hi-only) -> g_v2.
// grid (8 ltiles, 64 bg, 3 cv), 256 thr = 8 warps.
// ---------------------------------------------------------------------------
#define OFF_RAW 0                           // xs [64 i][134 f]   = 34,304 B
#define OFF_XH  34304                       // xp_hi [132][36] f2 = 38,016 B
#define OFF_XL  (OFF_XH + 38016)
#define OFF_WH  (OFF_XL + 38016)            // wp_hi [192][36] f2 = 55,296 B
#define OFF_WL  (OFF_WH + 55296)
#define SMEM_CONV (OFF_WL + 55296)          // 220,928 B

__global__ __launch_bounds__(256)
void conv_mma(const float* __restrict__ qin, const float* __restrict__ kin)
{
    extern __shared__ __align__(16) char sm[];
    u32 smb = smem_u32(sm);
    float*  xs = (float*) (sm + OFF_RAW);
    float*  oT = (float*) (sm + OFF_RAW);   // reused after GEMM
    float2* XH = (float2*)(sm + OFF_XH);
    float2* XL = (float2*)(sm + OFF_XL);
    float2* WH = (float2*)(sm + OFF_WH);
    float2* WL = (float2*)(sm + OFF_WL);

    int tid  = threadIdx.x;
    int w    = tid >> 5;
    int lane = tid & 31;
    int g    = lane >> 2;
    int q4   = lane & 3;
    int lt   = blockIdx.x * 128;
    int bg   = blockIdx.y;
    int cv   = blockIdx.z;
    int b    = bg >> 3, gr = bg & 7;

    const float* xg = ((cv == 0) ? qin : kin) + (size_t)(b*NC + gr*64) * NL;

    // ---- cp.async weights ----
    {
        const char* wsh = (const char*)g_wp_h + (size_t)(cv*64 + gr)*192*288;
        const char* wsl = (const char*)g_wp_l + (size_t)(cv*64 + gr)*192*288;
        #pragma unroll
        for (int it = 0; it < 14; ++it) {
            int u = it*256 + tid;
            if (u < 3456) {
                asm volatile("cp.async.cg.shared.global [%0], [%1], 16;"
                             :: "r"(smb + OFF_WH + u*16), "l"(wsh + (size_t)u*16) : "memory");
                if (cv != 2)
                    asm volatile("cp.async.cg.shared.global [%0], [%1], 16;"
                                 :: "r"(smb + OFF_WL + u*16), "l"(wsl + (size_t)u*16) : "memory");
            }
        }
        asm volatile("cp.async.commit_group;" ::: "memory");
    }

    // ---- stage raw x tile [64 i][132 r] (reflect pad), coalesced ----
    #pragma unroll
    for (int it = 0; it < 32; ++it) {
        int u = it*256 + tid;
        int i = u >> 7, r = u & 127;
        int l = lt - 1 + r;
        l = (l < 0) ? 1 : ((l >= NL) ? (2*NL - 2 - l) : l);
        xs[i*134 + r] = xg[(size_t)i*NL + l];
    }
    {   // tail rows 128..131
        int i = tid >> 2, r = 128 + (tid & 3);
        int l = lt - 1 + r;
        l = (l < 0) ? 1 : ((l >= NL) ? (2*NL - 2 - l) : l);
        xs[i*134 + r] = xg[(size_t)i*NL + l];
    }
    __syncthreads();

    // ---- transpose + tf32 split: fs = 8k + 2q + h, i = 8k + q + 4h ----
    #pragma unroll
    for (int it = 0; it < 33; ++it) {
        int u = it*256 + tid;             // < 8448 = 132*64
        int r = u >> 6, fs = u & 63;
        int k = fs >> 3, q = (fs >> 1) & 3, h = fs & 1;
        int i = 8*k + q + 4*h;
        float v = xs[i*134 + r];
        float hv = tf32hi(v);
        ((float*)XH)[r*72 + fs] = hv;
        ((float*)XL)[r*72 + fs] = v - hv;
    }
    asm volatile("cp.async.wait_group 0;" ::: "memory");
    __syncthreads();

    // ---- GEMM: warp w owns l-strip rows [w*16, +16) ----
    float oacc[8][4];
    #pragma unroll
    for (int n = 0; n < 8; ++n)
        #pragma unroll
        for (int e = 0; e < 4; ++e) oacc[n][e] = 0.f;

    int base = w*16 + g;
    #pragma unroll
    for (int t = 0; t < 3; ++t) {
        #pragma unroll
        for (int k = 0; k < 8; ++k) {
            float2 ah0 = XH[(base + t    )*36 + k*4 + q4];
            float2 ah1 = XH[(base + t + 8)*36 + k*4 + q4];
            float2 al0 = XL[(base + t    )*36 + k*4 + q4];
            float2 al1 = XL[(base + t + 8)*36 + k*4 + q4];
            u32 ahi[4] = {__float_as_uint(ah0.x), __float_as_uint(ah1.x),
                          __float_as_uint(ah0.y), __float_as_uint(ah1.y)};
            u32 alo[4] = {__float_as_uint(al0.x), __float_as_uint(al1.x),
                          __float_as_uint(al0.y), __float_as_uint(al1.y)};
            #pragma unroll
            for (int n = 0; n < 8; ++n) {
                int ro = (t*64 + 8*n + g)*36 + k*4 + q4;
                float2 bh = WH[ro];
                u32 b0 = __float_as_uint(bh.x), b1 = __float_as_uint(bh.y);
                mma8(oacc[n], ahi, b0, b1);
                mma8(oacc[n], alo, b0, b1);
                if (cv != 2) {
                    float2 bl = WL[ro];
                    mma8(oacc[n], ahi,
                         __float_as_uint(bl.x), __float_as_uint(bl.y));
                }
            }
        }
    }

    // ---- store accumulators to smem oT[c][134 + l] ----
    {
        int l0 = base, l1 = base + 8;
        #pragma unroll
        for (int n = 0; n < 8; ++n) {
            int c0 = 8*n + 2*q4;
            oT[(c0    )*134 + l0] = oacc[n][0];
            oT[(c0 + 1)*134 + l0] = oacc[n][1];
            oT[(c0    )*134 + l1] = oacc[n][2];
            oT[(c0 + 1)*134 + l1] = oacc[n][3];
        }
    }
    __syncthreads();

    // ---- pack epilogue ----
    if (cv != 2) {
        // float4 {h0, h1, l0, l1} -> g_q4 / g_k4
        float4* dst = ((cv == 0) ? g_q4 : g_k4) + (size_t)bg*NL*32;
        #pragma unroll
        for (int it = 0; it < 16; ++it) {
            int u  = it*256 + tid;        // < 4096
            int l  = u >> 5, kq = u & 31;
            int d0 = ((kq >> 2) << 3) | (kq & 3);
            float f0 = oT[(d0    )*134 + l];
            float f1 = oT[(d0 + 4)*134 + l];
            float h0 = tf32hi(f0), h1 = tf32hi(f1);
            dst[(size_t)(lt + l)*32 + kq] = make_float4(h0, h1, f0 - h0, f1 - h1);
        }
    } else {
        float2* vh = g_v2 + (size_t)bg*64*512;
        #pragma unroll
        for (int it = 0; it < 16; ++it) {
            int u  = it*256 + tid;        // < 4096
            int c  = u >> 6;
            int gp = (u >> 2) & 15, j = u & 3;
            float v0 = oT[c*134 + gp*8 + j];
            float v1 = oT[c*134 + gp*8 + j + 4];
            vh[(size_t)c*512 + ((lt >> 3) + gp)*4 + j] =
                make_float2(tf32hi(v0), tf32hi(v1));
        }
    }
}

// ---------------------------------------------------------------------------
// Causal attention (R12): mma.sync tf32, QK x3 / PV x2. K packed float4 ->
// one LDS.128 per B-fragment; cp.async double-buffered staging.
// ---------------------------------------------------------------------------
#define KPIT4 36                       // float4 pitch per packed K smem row
#define KSTG_BYTES (64*KPIT4*16)       // 36,864
#define VPIT2 36
#define VSTG_BYTES (64*VPIT2*8)        // 18,432
#define STAGE_BYTES (KSTG_BYTES + VSTG_BYTES)   // 55,296
#define SMEM_ATTN (2*STAGE_BYTES)               // 110,592

__global__ __launch_bounds__(256)
void attn_kernel()
{
    extern __shared__ __align__(16) char smraw[];
    u32 smb = smem_u32(smraw);

    int tid  = threadIdx.x;
    int w    = tid >> 5;
    int lane = tid & 31;
    int g    = lane >> 2;
    int q4   = lane & 3;
    int bh   = blockIdx.y;
    int qt   = 7 - blockIdx.x;
    int row0 = qt * 128;

    // ---- Q fragments from packed g_q4 (1 LDG.128 per row per k) ----
    const float4* qp = g_q4 + (size_t)bh*NL*32;
    int rbl = w*16 + g;
    u32 qAhi[8][4], qAlo[8][4];
    #pragma unroll
    for (int k = 0; k < 8; ++k) {
        float4 f0 = qp[(size_t)(row0+rbl  )*32 + k*4 + q4];
        float4 f1 = qp[(size_t)(row0+rbl+8)*32 + k*4 + q4];
        qAhi[k][0] = __float_as_uint(f0.x);
        qAhi[k][1] = __float_as_uint(f1.x);
        qAhi[k][2] = __float_as_uint(f0.y);
        qAhi[k][3] = __float_as_uint(f1.y);
        qAlo[k][0] = __float_as_uint(f0.z);
        qAlo[k][1] = __float_as_uint(f1.z);
        qAlo[k][2] = __float_as_uint(f0.w);
        qAlo[k][3] = __float_as_uint(f1.w);
    }

    float oacc[8][4];
    #pragma unroll
    for (int n = 0; n < 8; ++n)
        #pragma unroll
        for (int e = 0; e < 4; ++e) oacc[n][e] = 0.f;
    float s0 = 0.f, s1 = 0.f;

    int rbase = row0 + rbl;
    int nkt   = 2*qt + 2;
    int src0  = (lane & ~3) | (q4 >> 1);
    int src1  = src0 + 2;

    const char* k4g = (const char*)(g_k4 + (size_t)bh*NL*32);
    const char* vhg = (const char*)(g_v2 + (size_t)bh*64*512);

    auto stage = [&](int kt, int buf) {
        u32 base = smb + buf*STAGE_BYTES;
        #pragma unroll
        for (int i = 0; i < 12; ++i) {
            int u = i*256 + tid;                    // < 3072
            u32 dst; const char* src;
            if (u < 2048) {                         // K: 64 rows x 512B
                int r = u >> 5, c16 = u & 31;
                dst = base + r*(KPIT4*16) + c16*16;
                src = k4g + ((size_t)(kt*64 + r)*32)*16 + c16*16;
            } else {                                // V: 64 rows x 256B
                int v = u - 2048;
                int r = v >> 4, c16 = v & 15;
                dst = base + KSTG_BYTES + r*(VPIT2*8) + c16*16;
                src = vhg + ((size_t)r*512 + kt*32)*8 + c16*16;
            }
            asm volatile("cp.async.cg.shared.global [%0], [%1], 16;"
                         :: "r"(dst), "l"(src) : "memory");
        }
        asm volatile("cp.async.commit_group;" ::: "memory");
    };

    stage(0, 0);

    for (int kt = 0; kt < nkt; ++kt) {
        int buf = kt & 1;
        __syncthreads();
        if (kt + 1 < nkt) {
            stage(kt + 1, (kt + 1) & 1);
            asm volatile("cp.async.wait_group 1;" ::: "memory");
        } else {
            asm volatile("cp.async.wait_group 0;" ::: "memory");
        }
        __syncthreads();

        const float4* K4 = (const float4*)(smraw + buf*STAGE_BYTES);
        const float2* Vh = (const float2*)(smraw + buf*STAGE_BYTES + KSTG_BYTES);

        // ---- S = Q K^T (x3): B frag = ONE LDS.128 ----
        float sc[8][4];
        #pragma unroll
        for (int n = 0; n < 8; ++n)
            #pragma unroll
            for (int e = 0; e < 4; ++e) sc[n][e] = 0.f;

        #pragma unroll
        for (int k = 0; k < 8; ++k) {
            #pragma unroll
            for (int n = 0; n < 8; ++n) {
                float4 kf = K4[(8*n + g)*KPIT4 + k*4 + q4];
                u32 bh0 = __float_as_uint(kf.x), bh1 = __float_as_uint(kf.y);
                mma8(sc[n], qAhi[k], bh0, bh1);
                mma8(sc[n], qAlo[k], bh0, bh1);
                mma8(sc[n], qAhi[k],
                     __float_as_uint(kf.z), __float_as_uint(kf.w));
            }
        }

        // ---- softmax: exp-direct + causal mask ----
        #pragma unroll
        for (int n = 0; n < 8; ++n) {
            int cbase = kt*64 + 8*n + 2*q4;
            #pragma unroll
            for (int e = 0; e < 4; ++e) {
                int r = rbase + ((e >> 1) << 3);
                int c = cbase + (e & 1);
                float p = (c > r) ? 0.f : __expf(sc[n][e]);
                sc[n][e] = p;
                if (e < 2) s0 += p; else s1 += p;
            }
        }

        // ---- O += P V^T (x2); P acc->A frag via quad shuffles ----
        #pragma unroll
        for (int kk = 0; kk < 8; ++kk) {
            float v00 = __shfl_sync(0xffffffffu, sc[kk][0], src0);
            float v01 = __shfl_sync(0xffffffffu, sc[kk][1], src0);
            float v20 = __shfl_sync(0xffffffffu, sc[kk][2], src0);
            float v21 = __shfl_sync(0xffffffffu, sc[kk][3], src0);
            float w00 = __shfl_sync(0xffffffffu, sc[kk][0], src1);
            float w01 = __shfl_sync(0xffffffffu, sc[kk][1], src1);
            float w20 = __shfl_sync(0xffffffffu, sc[kk][2], src1);
            float w21 = __shfl_sync(0xffffffffu, sc[kk][3], src1);
            bool odd = (q4 & 1);
            float a[4];
            a[0] = odd ? v01 : v00;
            a[1] = odd ? v21 : v20;
            a[2] = odd ? w01 : w00;
            a[3] = odd ? w21 : w20;
            u32 pahi[4], palo[4];
            #pragma unroll
            for (int e = 0; e < 4; ++e) {
                float h = tf32hi(a[e]);
                pahi[e] = __float_as_uint(h);
                palo[e] = __float_as_uint(a[e] - h);
            }
            #pragma unroll
            for (int n = 0; n < 8; ++n) {
                float2 bv = Vh[(8*n + g)*VPIT2 + kk*4 + q4];
                u32 b0 = __float_as_uint(bv.x), b1 = __float_as_uint(bv.y);
                mma8(oacc[n], pahi, b0, b1);
                mma8(oacc[n], palo, b0, b1);
            }
        }
    }

    s0 += __shfl_xor_sync(0xffffffffu, s0, 1);
    s0 += __shfl_xor_sync(0xffffffffu, s0, 2);
    s1 += __shfl_xor_sync(0xffffffffu, s1, 1);
    s1 += __shfl_xor_sync(0xffffffffu, s1, 2);
    float inv0 = 1.f / s0, inv1 = 1.f / s1;

    int b = bh >> 3, h = bh & 7;
    float* Ob0 = g_o + ((size_t)(b*NL + rbase    ))*NC + h*ND;
    float* Ob1 = g_o + ((size_t)(b*NL + rbase + 8))*NC + h*ND;
    #pragma unroll
    for (int n = 0; n < 8; ++n) {
        int d = 8*n + 2*q4;
        *(float2*)(Ob0 + d) = make_float2(oacc[n][0]*inv0, oacc[n][1]*inv0);
        *(float2*)(Ob1 + d) = make_float2(oacc[n][2]*inv1, oacc[n][3]*inv1);
    }
}

// ---------------------------------------------------------------------------
// Residual add + LayerNorm over channel, transposed-tile version (unchanged).
// ---------------------------------------------------------------------------
#define TL 16
__global__ __launch_bounds__(128)
void ln_kernel(const float* __restrict__ init, const float* __restrict__ gamma,
               const float* __restrict__ beta, float* __restrict__ y)
{
    __shared__ float xt[TL][NC + 4];

    int blk = blockIdx.x;
    int b   = blk >> 6;
    int lt  = (blk & 63) * TL;
    int tid = threadIdx.x;

    const float* ib = init + (size_t)b * NC * NL + lt;
    float*       yb = y    + (size_t)b * NC * NL + lt;

    for (int i = tid; i < NC * (TL/4); i += 128) {
        int c = i >> 2, j = i & 3;
        float4 v = *(const float4*)(ib + (size_t)c * NL + 4*j);
        xt[4*j+0][c] = v.x; xt[4*j+1][c] = v.y;
        xt[4*j+2][c] = v.z; xt[4*j+3][c] = v.w;
    }
    __syncthreads();

    int w = tid >> 5, lane = tid & 31;
    const float* ob_base = g_o + ((size_t)(b*NL + lt)) * NC;
    for (int r = w; r < TL; r += 4) {
        const float4* orow = (const float4*)(ob_base + (size_t)r * NC);
        float4 xv[4];
        float s1 = 0.f, s2 = 0.f;
        #pragma unroll
        for (int kk = 0; kk < 4; ++kk) {
            int c4 = lane + 32*kk;
            float4 ov = orow[c4];
            float4 iv = *(const float4*)(&xt[r][4*c4]);
            xv[kk] = make_float4(ov.x+iv.x, ov.y+iv.y, ov.z+iv.z, ov.w+iv.w);
            s1 += xv[kk].x + xv[kk].y + xv[kk].z + xv[kk].w;
            s2 += xv[kk].x*xv[kk].x + xv[kk].y*xv[kk].y
                + xv[kk].z*xv[kk].z + xv[kk].w*xv[kk].w;
        }
        #pragma unroll
        for (int off = 16; off; off >>= 1) {
            s1 += __shfl_xor_sync(0xffffffffu, s1, off);
            s2 += __shfl_xor_sync(0xffffffffu, s2, off);
        }
        float mu   = s1 * (1.f/512.f);
        float var  = s2 * (1.f/512.f) - mu*mu;
        float rstd = rsqrtf(var + 1e-5f);

        #pragma unroll
        for (int kk = 0; kk < 4; ++kk) {
            int c4 = lane + 32*kk;
            float4 gv = ((const float4*)gamma)[c4];
            float4 bv = ((const float4*)beta)[c4];
            float4 r4;
            r4.x = (xv[kk].x - mu)*rstd*gv.x + bv.x;
            r4.y = (xv[kk].y - mu)*rstd*gv.y + bv.y;
            r4.z = (xv[kk].z - mu)*rstd*gv.z + bv.z;
            r4.w = (xv[kk].w - mu)*rstd*gv.w + bv.w;
            *(float4*)(&xt[r][4*c4]) = r4;
        }
    }
    __syncthreads();

    for (int i = tid; i < NC * (TL/4); i += 128) {
        int c = i >> 2, j = i & 3;
        float4 v = make_float4(xt[4*j+0][c], xt[4*j+1][c],
                               xt[4*j+2][c], xt[4*j+3][c]);
        *(float4*)(yb + (size_t)c * NL + 4*j) = v;
    }
}

// ---------------------------------------------------------------------------
extern "C" void kernel_launch(void* const* d_in, const int* in_sizes, int n_in,
                              void* d_out, int out_size)
{
    const float* q     = (const float*)d_in[0];
    const float* k     = (const float*)d_in[1];
    // d_in[2] = mask — causal, handled analytically
    const float* wq    = (const float*)d_in[3];
    const float* wk    = (const float*)d_in[4];
    const float* wv    = (const float*)d_in[5];
    const float* gamma = (const float*)d_in[6];
    const float* beta  = (const float*)d_in[7];
    float* out = (float*)d_out;

    cudaFuncSetAttribute(conv_mma,
                         cudaFuncAttributeMaxDynamicSharedMemorySize, SMEM_CONV);
    cudaFuncSetAttribute(attn_kernel,
                         cudaFuncAttributeMaxDynamicSharedMemorySize, SMEM_ATTN);

    pack_w<<<dim3(64, 3), 256>>>(wq, wk, wv);
    conv_mma<<<dim3(8, 64, 3), 256, SMEM_CONV>>>(q, k);
    attn_kernel<<<dim3(8, NB*NH), 256, SMEM_ATTN>>>();
    ln_kernel<<<NB * (NL/TL), 128>>>(q, gamma, beta, out);
}

// round 14
// speedup vs baseline: 1.5450x; 1.0907x over previous
#include <cuda_runtime.h>

#define NB 8
#define NC 512
#define NL 1024
#define NH 8
#define ND 64

typedef unsigned long long u64;
typedef unsigned int u32;

// ---------------- scratch (allocation-free rule) ---------------------------
// Q/K: tf32 packed [bh][row][k(8)][q4(4)] float4 {hi(d0), hi(d0+4), lo(d0), lo(d0+4)},
// d0 = 8k + q4.
__device__ float4 g_q4[NB*NH*NL*32];
__device__ float4 g_k4[NB*NH*NL*32];
// V: tf32 hi only, [bh][d][gp(128)][j(4)] float2 {v(d, 8gp+j), v(d, 8gp+j+4)}
__device__ float2 g_v2 [NB*NH*64*512];
__device__ float  g_o  [NB*NL*NC];     // attention output, [b][l][c]
// weights pre-packed: [cv][g][t*64+c][36] f2 pairs over i {w(8k+q4), w(8k+q4+4)}
__device__ float2 g_wp_h[3*64*192*36];
__device__ float2 g_wp_l[3*64*192*36];

// ---------------- tensor helpers (legacy mma.sync on sm_103) ---------------
__device__ __forceinline__ float tf32hi(float x) {
    u32 r; asm("cvt.rna.tf32.f32 %0, %1;" : "=r"(r) : "f"(x));
    return __uint_as_float(r);
}
__device__ __forceinline__ void mma8(float d[4], const u32 a[4], u32 b0, u32 b1) {
    asm volatile("mma.sync.aligned.m16n8k8.row.col.f32.tf32.tf32.f32 "
        "{%0,%1,%2,%3}, {%4,%5,%6,%7}, {%8,%9}, {%0,%1,%2,%3};"
        : "+f"(d[0]), "+f"(d[1]), "+f"(d[2]), "+f"(d[3])
        : "r"(a[0]), "r"(a[1]), "r"(a[2]), "r"(a[3]), "r"(b0), "r"(b1));
}
__device__ __forceinline__ u32 smem_u32(const void* p) {
    u32 a; asm("{ .reg .u64 t; cvta.to.shared.u64 t, %1; cvt.u32.u64 %0, t; }"
               : "=r"(a) : "l"(p)); return a;
}

// ---------------------------------------------------------------------------
// pack_w: weights -> pair-packed tf32 hi/lo, [cv][g][t*64+c][36] f2.
// Q weights (cv=0) pre-scaled by 1/sqrt(8). grid (64, 3) x 256 threads.
// ---------------------------------------------------------------------------
__global__ void pack_w(const float* __restrict__ wq, const float* __restrict__ wk,
                       const float* __restrict__ wv)
{
    int g  = blockIdx.x;
    int cv = blockIdx.y;
    const float* w = (cv == 0) ? wq : (cv == 1) ? wk : wv;
    float s = (cv == 0) ? 0.35355339059327373f : 1.0f;

    int tid = threadIdx.x;
    #pragma unroll
    for (int it = 0; it < 24; ++it) {
        int u  = it*256 + tid;            // < 6144
        int r  = u >> 5;                  // t*64 + c
        int k4 = u & 31;
        int t  = r >> 6, c = r & 63;
        int i0 = ((k4 >> 2) << 3) | (k4 & 3);
        float v0 = w[(size_t)((g*64 + c)*64 + i0    )*3 + t] * s;
        float v1 = w[(size_t)((g*64 + c)*64 + i0 + 4)*3 + t] * s;
        float h0 = tf32hi(v0), h1 = tf32hi(v1);
        size_t base = (size_t)((cv*64 + g)*192 + r)*36 + k4;
        g_wp_h[base] = make_float2(h0, h1);
        g_wp_l[base] = make_float2(v0 - h0, v1 - h1);
    }
}

// ---------------------------------------------------------------------------
// conv_mma (R11/R13): grouped conv1d as tensor GEMM, uniform grid.
// cv=0(Q),1(K): x3 -> float4-packed g_q4/g_k4.  cv=2(V): x2 -> g_v2.
// grid (8 ltiles, 64 bg, 3 cv), 256 thr = 8 warps.
// ---------------------------------------------------------------------------
#define OFF_RAW 0                           // xs [64 i][134 f]   = 34,304 B
#define OFF_XH  34304                       // xp_hi [132][36] f2 = 38,016 B
#define OFF_XL  (OFF_XH + 38016)
#define OFF_WH  (OFF_XL + 38016)            // wp_hi [192][36] f2 = 55,296 B
#define OFF_WL  (OFF_WH + 55296)
#define SMEM_CONV (OFF_WL + 55296)          // 220,928 B

__global__ __launch_bounds__(256)
void conv_mma(const float* __restrict__ qin, const float* __restrict__ kin)
{
    extern __shared__ __align__(16) char sm[];
    u32 smb = smem_u32(sm);
    float*  xs = (float*) (sm + OFF_RAW);
    float*  oT = (float*) (sm + OFF_RAW);   // reused after GEMM
    float2* XH = (float2*)(sm + OFF_XH);
    float2* XL = (float2*)(sm + OFF_XL);
    float2* WH = (float2*)(sm + OFF_WH);
    float2* WL = (float2*)(sm + OFF_WL);

    int tid  = threadIdx.x;
    int w    = tid >> 5;
    int lane = tid & 31;
    int g    = lane >> 2;
    int q4   = lane & 3;
    int lt   = blockIdx.x * 128;
    int bg   = blockIdx.y;
    int cv   = blockIdx.z;
    int b    = bg >> 3, gr = bg & 7;

    const float* xg = ((cv == 0) ? qin : kin) + (size_t)(b*NC + gr*64) * NL;

    // ---- cp.async weights ----
    {
        const char* wsh = (const char*)g_wp_h + (size_t)(cv*64 + gr)*192*288;
        const char* wsl = (const char*)g_wp_l + (size_t)(cv*64 + gr)*192*288;
        #pragma unroll
        for (int it = 0; it < 14; ++it) {
            int u = it*256 + tid;
            if (u < 3456) {
                asm volatile("cp.async.cg.shared.global [%0], [%1], 16;"
                             :: "r"(smb + OFF_WH + u*16), "l"(wsh + (size_t)u*16) : "memory");
                if (cv != 2)
                    asm volatile("cp.async.cg.shared.global [%0], [%1], 16;"
                                 :: "r"(smb + OFF_WL + u*16), "l"(wsl + (size_t)u*16) : "memory");
            }
        }
        asm volatile("cp.async.commit_group;" ::: "memory");
    }

    // ---- stage raw x tile [64 i][132 r] (reflect pad), coalesced ----
    #pragma unroll
    for (int it = 0; it < 32; ++it) {
        int u = it*256 + tid;
        int i = u >> 7, r = u & 127;
        int l = lt - 1 + r;
        l = (l < 0) ? 1 : ((l >= NL) ? (2*NL - 2 - l) : l);
        xs[i*134 + r] = xg[(size_t)i*NL + l];
    }
    {   // tail rows 128..131
        int i = tid >> 2, r = 128 + (tid & 3);
        int l = lt - 1 + r;
        l = (l < 0) ? 1 : ((l >= NL) ? (2*NL - 2 - l) : l);
        xs[i*134 + r] = xg[(size_t)i*NL + l];
    }
    __syncthreads();

    // ---- transpose + tf32 split: fs = 8k + 2q + h, i = 8k + q + 4h ----
    #pragma unroll
    for (int it = 0; it < 33; ++it) {
        int u = it*256 + tid;             // < 8448 = 132*64
        int r = u >> 6, fs = u & 63;
        int k = fs >> 3, q = (fs >> 1) & 3, h = fs & 1;
        int i = 8*k + q + 4*h;
        float v = xs[i*134 + r];
        float hv = tf32hi(v);
        ((float*)XH)[r*72 + fs] = hv;
        ((float*)XL)[r*72 + fs] = v - hv;
    }
    asm volatile("cp.async.wait_group 0;" ::: "memory");
    __syncthreads();

    // ---- GEMM: warp w owns l-strip rows [w*16, +16) ----
    float oacc[8][4];
    #pragma unroll
    for (int n = 0; n < 8; ++n)
        #pragma unroll
        for (int e = 0; e < 4; ++e) oacc[n][e] = 0.f;

    int base = w*16 + g;
    #pragma unroll
    for (int t = 0; t < 3; ++t) {
        #pragma unroll
        for (int k = 0; k < 8; ++k) {
            float2 ah0 = XH[(base + t    )*36 + k*4 + q4];
            float2 ah1 = XH[(base + t + 8)*36 + k*4 + q4];
            float2 al0 = XL[(base + t    )*36 + k*4 + q4];
            float2 al1 = XL[(base + t + 8)*36 + k*4 + q4];
            u32 ahi[4] = {__float_as_uint(ah0.x), __float_as_uint(ah1.x),
                          __float_as_uint(ah0.y), __float_as_uint(ah1.y)};
            u32 alo[4] = {__float_as_uint(al0.x), __float_as_uint(al1.x),
                          __float_as_uint(al0.y), __float_as_uint(al1.y)};
            #pragma unroll
            for (int n = 0; n < 8; ++n) {
                int ro = (t*64 + 8*n + g)*36 + k*4 + q4;
                float2 bh = WH[ro];
                u32 b0 = __float_as_uint(bh.x), b1 = __float_as_uint(bh.y);
                mma8(oacc[n], ahi, b0, b1);
                mma8(oacc[n], alo, b0, b1);
                if (cv != 2) {
                    float2 bl = WL[ro];
                    mma8(oacc[n], ahi,
                         __float_as_uint(bl.x), __float_as_uint(bl.y));
                }
            }
        }
    }

    // ---- store accumulators to smem oT[c][134 + l] ----
    {
        int l0 = base, l1 = base + 8;
        #pragma unroll
        for (int n = 0; n < 8; ++n) {
            int c0 = 8*n + 2*q4;
            oT[(c0    )*134 + l0] = oacc[n][0];
            oT[(c0 + 1)*134 + l0] = oacc[n][1];
            oT[(c0    )*134 + l1] = oacc[n][2];
            oT[(c0 + 1)*134 + l1] = oacc[n][3];
        }
    }
    __syncthreads();

    // ---- pack epilogue ----
    if (cv != 2) {
        float4* dst = ((cv == 0) ? g_q4 : g_k4) + (size_t)bg*NL*32;
        #pragma unroll
        for (int it = 0; it < 16; ++it) {
            int u  = it*256 + tid;        // < 4096
            int l  = u >> 5, kq = u & 31;
            int d0 = ((kq >> 2) << 3) | (kq & 3);
            float f0 = oT[(d0    )*134 + l];
            float f1 = oT[(d0 + 4)*134 + l];
            float h0 = tf32hi(f0), h1 = tf32hi(f1);
            dst[(size_t)(lt + l)*32 + kq] = make_float4(h0, h1, f0 - h0, f1 - h1);
        }
    } else {
        float2* vh = g_v2 + (size_t)bg*64*512;
        #pragma unroll
        for (int it = 0; it < 16; ++it) {
            int u  = it*256 + tid;        // < 4096
            int c  = u >> 6;
            int gp = (u >> 2) & 15, j = u & 3;
            float v0 = oT[c*134 + gp*8 + j];
            float v1 = oT[c*134 + gp*8 + j + 4];
            vh[(size_t)c*512 + ((lt >> 3) + gp)*4 + j] =
                make_float2(tf32hi(v0), tf32hi(v1));
        }
    }
}

// ---------------------------------------------------------------------------
// Causal attention R14: fused per-key-octet loop (QK x3 -> softmax -> PV x1),
// warp-uniform mask fast-paths, 2 CTAs/SM. cp.async double-buffered staging.
// ---------------------------------------------------------------------------
#define KPIT4 36                       // float4 pitch per packed K smem row
#define KSTG_BYTES (64*KPIT4*16)       // 36,864
#define VPIT2 36
#define VSTG_BYTES (64*VPIT2*8)        // 18,432
#define STAGE_BYTES (KSTG_BYTES + VSTG_BYTES)   // 55,296
#define SMEM_ATTN (2*STAGE_BYTES)               // 110,592

__global__ __launch_bounds__(256, 2)
void attn_kernel()
{
    extern __shared__ __align__(16) char smraw[];
    u32 smb = smem_u32(smraw);

    int tid  = threadIdx.x;
    int w    = tid >> 5;
    int lane = tid & 31;
    int g    = lane >> 2;
    int q4   = lane & 3;
    int bh   = blockIdx.y;
    int qt   = 7 - blockIdx.x;
    int row0 = qt * 128;

    // ---- Q fragments from packed g_q4 ----
    const float4* qp = g_q4 + (size_t)bh*NL*32;
    int rbl = w*16 + g;
    u32 qAhi[8][4], qAlo[8][4];
    #pragma unroll
    for (int k = 0; k < 8; ++k) {
        float4 f0 = qp[(size_t)(row0+rbl  )*32 + k*4 + q4];
        float4 f1 = qp[(size_t)(row0+rbl+8)*32 + k*4 + q4];
        qAhi[k][0] = __float_as_uint(f0.x);
        qAhi[k][1] = __float_as_uint(f1.x);
        qAhi[k][2] = __float_as_uint(f0.y);
        qAhi[k][3] = __float_as_uint(f1.y);
        qAlo[k][0] = __float_as_uint(f0.z);
        qAlo[k][1] = __float_as_uint(f1.z);
        qAlo[k][2] = __float_as_uint(f0.w);
        qAlo[k][3] = __float_as_uint(f1.w);
    }

    float oacc[8][4];
    #pragma unroll
    for (int n = 0; n < 8; ++n)
        #pragma unroll
        for (int e = 0; e < 4; ++e) oacc[n][e] = 0.f;
    float s0 = 0.f, s1 = 0.f;

    int rbase = row0 + rbl;
    int wmin  = row0 + w*16;          // warp's min q row
    int wmax  = wmin + 15;            // warp's max q row
    int nkt   = 2*qt + 2;
    int src0  = (lane & ~3) | (q4 >> 1);
    int src1  = src0 + 2;

    const char* k4g = (const char*)(g_k4 + (size_t)bh*NL*32);
    const char* vhg = (const char*)(g_v2 + (size_t)bh*64*512);

    auto stage = [&](int kt, int buf) {
        u32 base = smb + buf*STAGE_BYTES;
        #pragma unroll
        for (int i = 0; i < 12; ++i) {
            int u = i*256 + tid;                    // < 3072
            u32 dst; const char* src;
            if (u < 2048) {                         // K: 64 rows x 512B
                int r = u >> 5, c16 = u & 31;
                dst = base + r*(KPIT4*16) + c16*16;
                src = k4g + ((size_t)(kt*64 + r)*32)*16 + c16*16;
            } else {                                // V: 64 rows x 256B
                int v = u - 2048;
                int r = v >> 4, c16 = v & 15;
                dst = base + KSTG_BYTES + r*(VPIT2*8) + c16*16;
                src = vhg + ((size_t)r*512 + kt*32)*8 + c16*16;
            }
            asm volatile("cp.async.cg.shared.global [%0], [%1], 16;"
                         :: "r"(dst), "l"(src) : "memory");
        }
        asm volatile("cp.async.commit_group;" ::: "memory");
    };

    stage(0, 0);

    for (int kt = 0; kt < nkt; ++kt) {
        int buf = kt & 1;
        __syncthreads();
        if (kt + 1 < nkt) {
            stage(kt + 1, (kt + 1) & 1);
            asm volatile("cp.async.wait_group 1;" ::: "memory");
        } else {
            asm volatile("cp.async.wait_group 0;" ::: "memory");
        }
        __syncthreads();

        if (kt*64 > wmax) continue;   // tile fully masked for this warp

        const float4* K4 = (const float4*)(smraw + buf*STAGE_BYTES);
        const float2* Vh = (const float2*)(smraw + buf*STAGE_BYTES + KSTG_BYTES);

        #pragma unroll
        for (int kk = 0; kk < 8; ++kk) {
            int cb = kt*64 + 8*kk;            // octet base column
            if (cb > wmax) break;             // remaining octets fully masked

            // ---- QK for this key octet (x3 compensated, 2 chains) ----
            float scA[4] = {0.f, 0.f, 0.f, 0.f};
            float scB[4] = {0.f, 0.f, 0.f, 0.f};
            #pragma unroll
            for (int k = 0; k < 8; ++k) {
                float4 kf = K4[(8*kk + g)*KPIT4 + k*4 + q4];
                u32 bh0 = __float_as_uint(kf.x), bh1 = __float_as_uint(kf.y);
                mma8(scA, qAhi[k], bh0, bh1);
                mma8(scB, qAlo[k], bh0, bh1);
                mma8(scA, qAhi[k],
                     __float_as_uint(kf.z), __float_as_uint(kf.w));
            }

            // ---- softmax (exp-direct) with warp-uniform fast path ----
            float p[4];
            if (cb + 7 <= wmin) {             // fully unmasked octet
                #pragma unroll
                for (int e = 0; e < 4; ++e)
                    p[e] = __expf(scA[e] + scB[e]);
            } else {                          // diagonal octet: element mask
                #pragma unroll
                for (int e = 0; e < 4; ++e) {
                    int r = rbase + ((e >> 1) << 3);
                    int c = cb + 2*q4 + (e & 1);
                    p[e] = (c > r) ? 0.f : __expf(scA[e] + scB[e]);
                }
            }
            s0 += p[0] + p[1];
            s1 += p[2] + p[3];

            // ---- relayout P acc-frag -> A-frag via quad shuffles ----
            float v00 = __shfl_sync(0xffffffffu, p[0], src0);
            float v01 = __shfl_sync(0xffffffffu, p[1], src0);
            float v20 = __shfl_sync(0xffffffffu, p[2], src0);
            float v21 = __shfl_sync(0xffffffffu, p[3], src0);
            float w00 = __shfl_sync(0xffffffffu, p[0], src1);
            float w01 = __shfl_sync(0xffffffffu, p[1], src1);
            float w20 = __shfl_sync(0xffffffffu, p[2], src1);
            float w21 = __shfl_sync(0xffffffffu, p[3], src1);
            bool odd = (q4 & 1);
            u32 pa[4];
            pa[0] = __float_as_uint(tf32hi(odd ? v01 : v00));
            pa[1] = __float_as_uint(tf32hi(odd ? v21 : v20));
            pa[2] = __float_as_uint(tf32hi(odd ? w01 : w00));
            pa[3] = __float_as_uint(tf32hi(odd ? w21 : w20));

            // ---- PV x1 (P hi x V hi) ----
            #pragma unroll
            for (int n = 0; n < 8; ++n) {
                float2 bv = Vh[(8*n + g)*VPIT2 + kk*4 + q4];
                mma8(oacc[n], pa,
                     __float_as_uint(bv.x), __float_as_uint(bv.y));
            }
        }
    }

    // ---- finalize: quad-reduce row sums, normalize, write ----
    s0 += __shfl_xor_sync(0xffffffffu, s0, 1);
    s0 += __shfl_xor_sync(0xffffffffu, s0, 2);
    s1 += __shfl_xor_sync(0xffffffffu, s1, 1);
    s1 += __shfl_xor_sync(0xffffffffu, s1, 2);
    float inv0 = 1.f / s0, inv1 = 1.f / s1;

    int b = bh >> 3, h = bh & 7;
    float* Ob0 = g_o + ((size_t)(b*NL + rbase    ))*NC + h*ND;
    float* Ob1 = g_o + ((size_t)(b*NL + rbase + 8))*NC + h*ND;
    #pragma unroll
    for (int n = 0; n < 8; ++n) {
        int d = 8*n + 2*q4;
        *(float2*)(Ob0 + d) = make_float2(oacc[n][0]*inv0, oacc[n][1]*inv0);
        *(float2*)(Ob1 + d) = make_float2(oacc[n][2]*inv1, oacc[n][3]*inv1);
    }
}

// ---------------------------------------------------------------------------
// Residual add + LayerNorm over channel, transposed-tile version (unchanged).
// ---------------------------------------------------------------------------
#define TL 16
__global__ __launch_bounds__(128)
void ln_kernel(const float* __restrict__ init, const float* __restrict__ gamma,
               const float* __restrict__ beta, float* __restrict__ y)
{
    __shared__ float xt[TL][NC + 4];

    int blk = blockIdx.x;
    int b   = blk >> 6;
    int lt  = (blk & 63) * TL;
    int tid = threadIdx.x;

    const float* ib = init + (size_t)b * NC * NL + lt;
    float*       yb = y    + (size_t)b * NC * NL + lt;

    for (int i = tid; i < NC * (TL/4); i += 128) {
        int c = i >> 2, j = i & 3;
        float4 v = *(const float4*)(ib + (size_t)c * NL + 4*j);
        xt[4*j+0][c] = v.x; xt[4*j+1][c] = v.y;
        xt[4*j+2][c] = v.z; xt[4*j+3][c] = v.w;
    }
    __syncthreads();

    int w = tid >> 5, lane = tid & 31;
    const float* ob_base = g_o + ((size_t)(b*NL + lt)) * NC;
    for (int r = w; r < TL; r += 4) {
        const float4* orow = (const float4*)(ob_base + (size_t)r * NC);
        float4 xv[4];
        float s1 = 0.f, s2 = 0.f;
        #pragma unroll
        for (int kk = 0; kk < 4; ++kk) {
            int c4 = lane + 32*kk;
            float4 ov = orow[c4];
            float4 iv = *(const float4*)(&xt[r][4*c4]);
            xv[kk] = make_float4(ov.x+iv.x, ov.y+iv.y, ov.z+iv.z, ov.w+iv.w);
            s1 += xv[kk].x + xv[kk].y + xv[kk].z + xv[kk].w;
            s2 += xv[kk].x*xv[kk].x + xv[kk].y*xv[kk].y
                + xv[kk].z*xv[kk].z + xv[kk].w*xv[kk].w;
        }
        #pragma unroll
        for (int off = 16; off; off >>= 1) {
            s1 += __shfl_xor_sync(0xffffffffu, s1, off);
            s2 += __shfl_xor_sync(0xffffffffu, s2, off);
        }
        float mu   = s1 * (1.f/512.f);
        float var  = s2 * (1.f/512.f) - mu*mu;
        float rstd = rsqrtf(var + 1e-5f);

        #pragma unroll
        for (int kk = 0; kk < 4; ++kk) {
            int c4 = lane + 32*kk;
            float4 gv = ((const float4*)gamma)[c4];
            float4 bv = ((const float4*)beta)[c4];
            float4 r4;
            r4.x = (xv[kk].x - mu)*rstd*gv.x + bv.x;
            r4.y = (xv[kk].y - mu)*rstd*gv.y + bv.y;
            r4.z = (xv[kk].z - mu)*rstd*gv.z + bv.z;
            r4.w = (xv[kk].w - mu)*rstd*gv.w + bv.w;
            *(float4*)(&xt[r][4*c4]) = r4;
        }
    }
    __syncthreads();

    for (int i = tid; i < NC * (TL/4); i += 128) {
        int c = i >> 2, j = i & 3;
        float4 v = make_float4(xt[4*j+0][c], xt[4*j+1][c],
                               xt[4*j+2][c], xt[4*j+3][c]);
        *(float4*)(yb + (size_t)c * NL + 4*j) = v;
    }
}

// ---------------------------------------------------------------------------
extern "C" void kernel_launch(void* const* d_in, const int* in_sizes, int n_in,
                              void* d_out, int out_size)
{
    const float* q     = (const float*)d_in[0];
    const float* k     = (const float*)d_in[1];
    // d_in[2] = mask — causal, handled analytically
    const float* wq    = (const float*)d_in[3];
    const float* wk    = (const float*)d_in[4];
    const float* wv    = (const float*)d_in[5];
    const float* gamma = (const float*)d_in[6];
    const float* beta  = (const float*)d_in[7];
    float* out = (float*)d_out;

    cudaFuncSetAttribute(conv_mma,
                         cudaFuncAttributeMaxDynamicSharedMemorySize, SMEM_CONV);
    cudaFuncSetAttribute(attn_kernel,
                         cudaFuncAttributeMaxDynamicSharedMemorySize, SMEM_ATTN);

    pack_w<<<dim3(64, 3), 256>>>(wq, wk, wv);
    conv_mma<<<dim3(8, 64, 3), 256, SMEM_CONV>>>(q, k);
    attn_kernel<<<dim3(8, NB*NH), 256, SMEM_ATTN>>>();
    ln_kernel<<<NB * (NL/TL), 128>>>(q, gamma, beta, out);
}

// round 15
// speedup vs baseline: 1.6056x; 1.0392x over previous
#include <cuda_runtime.h>

#define NB 8
#define NC 512
#define NL 1024
#define NH 8
#define ND 64

typedef unsigned long long u64;
typedef unsigned int u32;

// ---------------- scratch (allocation-free rule) ---------------------------
// Q/K: tf32 packed [bh][row][k(8)][q4(4)] float4 {hi(d0), hi(d0+4), lo(d0), lo(d0+4)},
// d0 = 8k + q4.
__device__ float4 g_q4[NB*NH*NL*32];
__device__ float4 g_k4[NB*NH*NL*32];
// V: tf32 hi only, [bh][d][gp(128)][j(4)] float2 {v(d, 8gp+j), v(d, 8gp+j+4)}
__device__ float2 g_v2 [NB*NH*64*512];
__device__ float  g_o  [NB*NL*NC];     // attention output, [b][l][c]
// weights pre-packed: [cv][g][t*64+c][36] f2 pairs over i {w(8k+q4), w(8k+q4+4)}
__device__ float2 g_wp_h[3*64*192*36];
__device__ float2 g_wp_l[3*64*192*36];

// ---------------- tensor helpers (legacy mma.sync on sm_103) ---------------
__device__ __forceinline__ float tf32hi(float x) {
    u32 r; asm("cvt.rna.tf32.f32 %0, %1;" : "=r"(r) : "f"(x));
    return __uint_as_float(r);
}
__device__ __forceinline__ void mma8(float d[4], const u32 a[4], u32 b0, u32 b1) {
    asm volatile("mma.sync.aligned.m16n8k8.row.col.f32.tf32.tf32.f32 "
        "{%0,%1,%2,%3}, {%4,%5,%6,%7}, {%8,%9}, {%0,%1,%2,%3};"
        : "+f"(d[0]), "+f"(d[1]), "+f"(d[2]), "+f"(d[3])
        : "r"(a[0]), "r"(a[1]), "r"(a[2]), "r"(a[3]), "r"(b0), "r"(b1));
}
__device__ __forceinline__ u32 smem_u32(const void* p) {
    u32 a; asm("{ .reg .u64 t; cvta.to.shared.u64 t, %1; cvt.u32.u64 %0, t; }"
               : "=r"(a) : "l"(p)); return a;
}

// ---------------------------------------------------------------------------
// pack_w: weights -> pair-packed tf32 hi/lo, [cv][g][t*64+c][36] f2.
// Q weights (cv=0) pre-scaled by 1/sqrt(8). grid (64, 3) x 256 threads.
// ---------------------------------------------------------------------------
__global__ void pack_w(const float* __restrict__ wq, const float* __restrict__ wk,
                       const float* __restrict__ wv)
{
    int g  = blockIdx.x;
    int cv = blockIdx.y;
    const float* w = (cv == 0) ? wq : (cv == 1) ? wk : wv;
    float s = (cv == 0) ? 0.35355339059327373f : 1.0f;

    int tid = threadIdx.x;
    #pragma unroll
    for (int it = 0; it < 24; ++it) {
        int u  = it*256 + tid;            // < 6144
        int r  = u >> 5;                  // t*64 + c
        int k4 = u & 31;
        int t  = r >> 6, c = r & 63;
        int i0 = ((k4 >> 2) << 3) | (k4 & 3);
        float v0 = w[(size_t)((g*64 + c)*64 + i0    )*3 + t] * s;
        float v1 = w[(size_t)((g*64 + c)*64 + i0 + 4)*3 + t] * s;
        float h0 = tf32hi(v0), h1 = tf32hi(v1);
        size_t base = (size_t)((cv*64 + g)*192 + r)*36 + k4;
        g_wp_h[base] = make_float2(h0, h1);
        g_wp_l[base] = make_float2(v0 - h0, v1 - h1);
    }
}

// ---------------------------------------------------------------------------
// conv_mma: grouped conv1d as tensor GEMM; 2 l-tiles per block (W amortized).
// cv=0(Q),1(K): x3 -> float4-packed g_q4/g_k4.  cv=2(V): x2 -> g_v2.
// grid (4 lt-pairs, 64 bg, 3 cv), 256 thr = 8 warps. Uniform work per block.
// ---------------------------------------------------------------------------
#define OFF_RAW 0                           // xs [64 i][134 f]   = 34,304 B
#define OFF_XH  34304                       // xp_hi [132][36] f2 = 38,016 B
#define OFF_XL  (OFF_XH + 38016)
#define OFF_WH  (OFF_XL + 38016)            // wp_hi [192][36] f2 = 55,296 B
#define OFF_WL  (OFF_WH + 55296)
#define SMEM_CONV (OFF_WL + 55296)          // 220,928 B

__global__ __launch_bounds__(256)
void conv_mma(const float* __restrict__ qin, const float* __restrict__ kin)
{
    extern __shared__ __align__(16) char sm[];
    u32 smb = smem_u32(sm);
    float*  xs = (float*) (sm + OFF_RAW);
    float*  oT = (float*) (sm + OFF_RAW);   // reused after GEMM
    float2* XH = (float2*)(sm + OFF_XH);
    float2* XL = (float2*)(sm + OFF_XL);
    float2* WH = (float2*)(sm + OFF_WH);
    float2* WL = (float2*)(sm + OFF_WL);

    int tid  = threadIdx.x;
    int w    = tid >> 5;
    int lane = tid & 31;
    int g    = lane >> 2;
    int q4   = lane & 3;
    int bg   = blockIdx.y;
    int cv   = blockIdx.z;
    int b    = bg >> 3, gr = bg & 7;

    const float* xg = ((cv == 0) ? qin : kin) + (size_t)(b*NC + gr*64) * NL;

    // ---- cp.async weights (once per block) ----
    {
        const char* wsh = (const char*)g_wp_h + (size_t)(cv*64 + gr)*192*288;
        const char* wsl = (const char*)g_wp_l + (size_t)(cv*64 + gr)*192*288;
        #pragma unroll
        for (int it = 0; it < 14; ++it) {
            int u = it*256 + tid;
            if (u < 3456) {
                asm volatile("cp.async.cg.shared.global [%0], [%1], 16;"
                             :: "r"(smb + OFF_WH + u*16), "l"(wsh + (size_t)u*16) : "memory");
                if (cv != 2)
                    asm volatile("cp.async.cg.shared.global [%0], [%1], 16;"
                                 :: "r"(smb + OFF_WL + u*16), "l"(wsl + (size_t)u*16) : "memory");
            }
        }
        asm volatile("cp.async.commit_group;" ::: "memory");
    }

    int base = w*16 + g;

    for (int sub = 0; sub < 2; ++sub) {
        int lt = blockIdx.x * 256 + sub * 128;
        if (sub) __syncthreads();           // prior epilogue reads of oT done

        // ---- stage raw x tile [64 i][132 r] (reflect pad), coalesced ----
        #pragma unroll
        for (int it = 0; it < 32; ++it) {
            int u = it*256 + tid;
            int i = u >> 7, r = u & 127;
            int l = lt - 1 + r;
            l = (l < 0) ? 1 : ((l >= NL) ? (2*NL - 2 - l) : l);
            xs[i*134 + r] = xg[(size_t)i*NL + l];
        }
        {   // tail rows 128..131
            int i = tid >> 2, r = 128 + (tid & 3);
            int l = lt - 1 + r;
            l = (l < 0) ? 1 : ((l >= NL) ? (2*NL - 2 - l) : l);
            xs[i*134 + r] = xg[(size_t)i*NL + l];
        }
        __syncthreads();

        // ---- transpose + tf32 split: fs = 8k + 2q + h, i = 8k + q + 4h ----
        #pragma unroll
        for (int it = 0; it < 33; ++it) {
            int u = it*256 + tid;           // < 8448 = 132*64
            int r = u >> 6, fs = u & 63;
            int k = fs >> 3, q = (fs >> 1) & 3, h = fs & 1;
            int i = 8*k + q + 4*h;
            float v = xs[i*134 + r];
            float hv = tf32hi(v);
            ((float*)XH)[r*72 + fs] = hv;
            ((float*)XL)[r*72 + fs] = v - hv;
        }
        asm volatile("cp.async.wait_group 0;" ::: "memory");
        __syncthreads();

        // ---- GEMM: warp w owns l-strip rows [w*16, +16) ----
        float oacc[8][4];
        #pragma unroll
        for (int n = 0; n < 8; ++n)
            #pragma unroll
            for (int e = 0; e < 4; ++e) oacc[n][e] = 0.f;

        #pragma unroll
        for (int t = 0; t < 3; ++t) {
            #pragma unroll
            for (int k = 0; k < 8; ++k) {
                float2 ah0 = XH[(base + t    )*36 + k*4 + q4];
                float2 ah1 = XH[(base + t + 8)*36 + k*4 + q4];
                float2 al0 = XL[(base + t    )*36 + k*4 + q4];
                float2 al1 = XL[(base + t + 8)*36 + k*4 + q4];
                u32 ahi[4] = {__float_as_uint(ah0.x), __float_as_uint(ah1.x),
                              __float_as_uint(ah0.y), __float_as_uint(ah1.y)};
                u32 alo[4] = {__float_as_uint(al0.x), __float_as_uint(al1.x),
                              __float_as_uint(al0.y), __float_as_uint(al1.y)};
                #pragma unroll
                for (int n = 0; n < 8; ++n) {
                    int ro = (t*64 + 8*n + g)*36 + k*4 + q4;
                    float2 bh = WH[ro];
                    u32 b0 = __float_as_uint(bh.x), b1 = __float_as_uint(bh.y);
                    mma8(oacc[n], ahi, b0, b1);
                    mma8(oacc[n], alo, b0, b1);
                    if (cv != 2) {
                        float2 bl = WL[ro];
                        mma8(oacc[n], ahi,
                             __float_as_uint(bl.x), __float_as_uint(bl.y));
                    }
                }
            }
        }

        // ---- store accumulators to smem oT[c][134 + l] ----
        {
            int l0 = base, l1 = base + 8;
            #pragma unroll
            for (int n = 0; n < 8; ++n) {
                int c0 = 8*n + 2*q4;
                oT[(c0    )*134 + l0] = oacc[n][0];
                oT[(c0 + 1)*134 + l0] = oacc[n][1];
                oT[(c0    )*134 + l1] = oacc[n][2];
                oT[(c0 + 1)*134 + l1] = oacc[n][3];
            }
        }
        __syncthreads();

        // ---- pack epilogue ----
        if (cv != 2) {
            float4* dst = ((cv == 0) ? g_q4 : g_k4) + (size_t)bg*NL*32;
            #pragma unroll
            for (int it = 0; it < 16; ++it) {
                int u  = it*256 + tid;      // < 4096
                int l  = u >> 5, kq = u & 31;
                int d0 = ((kq >> 2) << 3) | (kq & 3);
                float f0 = oT[(d0    )*134 + l];
                float f1 = oT[(d0 + 4)*134 + l];
                float h0 = tf32hi(f0), h1 = tf32hi(f1);
                dst[(size_t)(lt + l)*32 + kq] = make_float4(h0, h1, f0 - h0, f1 - h1);
            }
        } else {
            float2* vh = g_v2 + (size_t)bg*64*512;
            #pragma unroll
            for (int it = 0; it < 16; ++it) {
                int u  = it*256 + tid;      // < 4096
                int c  = u >> 6;
                int gp = (u >> 2) & 15, j = u & 3;
                float v0 = oT[c*134 + gp*8 + j];
                float v1 = oT[c*134 + gp*8 + j + 4];
                vh[(size_t)c*512 + ((lt >> 3) + gp)*4 + j] =
                    make_float2(tf32hi(v0), tf32hi(v1));
            }
        }
    }
}

// ---------------------------------------------------------------------------
// Causal attention R15: R14 fused-octet loop with 3 balanced QK accumulator
// chains (3-way HMMA ILP). PV x1, warp-uniform mask fast-paths, 2 CTAs/SM.
// ---------------------------------------------------------------------------
#define KPIT4 36                       // float4 pitch per packed K smem row
#define KSTG_BYTES (64*KPIT4*16)       // 36,864
#define VPIT2 36
#define VSTG_BYTES (64*VPIT2*8)        // 18,432
#define STAGE_BYTES (KSTG_BYTES + VSTG_BYTES)   // 55,296
#define SMEM_ATTN (2*STAGE_BYTES)               // 110,592

__global__ __launch_bounds__(256, 2)
void attn_kernel()
{
    extern __shared__ __align__(16) char smraw[];
    u32 smb = smem_u32(smraw);

    int tid  = threadIdx.x;
    int w    = tid >> 5;
    int lane = tid & 31;
    int g    = lane >> 2;
    int q4   = lane & 3;
    int bh   = blockIdx.y;
    int qt   = 7 - blockIdx.x;
    int row0 = qt * 128;

    // ---- Q fragments from packed g_q4 ----
    const float4* qp = g_q4 + (size_t)bh*NL*32;
    int rbl = w*16 + g;
    u32 qAhi[8][4], qAlo[8][4];
    #pragma unroll
    for (int k = 0; k < 8; ++k) {
        float4 f0 = qp[(size_t)(row0+rbl  )*32 + k*4 + q4];
        float4 f1 = qp[(size_t)(row0+rbl+8)*32 + k*4 + q4];
        qAhi[k][0] = __float_as_uint(f0.x);
        qAhi[k][1] = __float_as_uint(f1.x);
        qAhi[k][2] = __float_as_uint(f0.y);
        qAhi[k][3] = __float_as_uint(f1.y);
        qAlo[k][0] = __float_as_uint(f0.z);
        qAlo[k][1] = __float_as_uint(f1.z);
        qAlo[k][2] = __float_as_uint(f0.w);
        qAlo[k][3] = __float_as_uint(f1.w);
    }

    float oacc[8][4];
    #pragma unroll
    for (int n = 0; n < 8; ++n)
        #pragma unroll
        for (int e = 0; e < 4; ++e) oacc[n][e] = 0.f;
    float s0 = 0.f, s1 = 0.f;

    int rbase = row0 + rbl;
    int wmin  = row0 + w*16;          // warp's min q row
    int wmax  = wmin + 15;            // warp's max q row
    int nkt   = 2*qt + 2;
    int src0  = (lane & ~3) | (q4 >> 1);
    int src1  = src0 + 2;

    const char* k4g = (const char*)(g_k4 + (size_t)bh*NL*32);
    const char* vhg = (const char*)(g_v2 + (size_t)bh*64*512);

    auto stage = [&](int kt, int buf) {
        u32 base = smb + buf*STAGE_BYTES;
        #pragma unroll
        for (int i = 0; i < 12; ++i) {
            int u = i*256 + tid;                    // < 3072
            u32 dst; const char* src;
            if (u < 2048) {                         // K: 64 rows x 512B
                int r = u >> 5, c16 = u & 31;
                dst = base + r*(KPIT4*16) + c16*16;
                src = k4g + ((size_t)(kt*64 + r)*32)*16 + c16*16;
            } else {                                // V: 64 rows x 256B
                int v = u - 2048;
                int r = v >> 4, c16 = v & 15;
                dst = base + KSTG_BYTES + r*(VPIT2*8) + c16*16;
                src = vhg + ((size_t)r*512 + kt*32)*8 + c16*16;
            }
            asm volatile("cp.async.cg.shared.global [%0], [%1], 16;"
                         :: "r"(dst), "l"(src) : "memory");
        }
        asm volatile("cp.async.commit_group;" ::: "memory");
    };

    stage(0, 0);

    for (int kt = 0; kt < nkt; ++kt) {
        int buf = kt & 1;
        __syncthreads();
        if (kt + 1 < nkt) {
            stage(kt + 1, (kt + 1) & 1);
            asm volatile("cp.async.wait_group 1;" ::: "memory");
        } else {
            asm volatile("cp.async.wait_group 0;" ::: "memory");
        }
        __syncthreads();

        if (kt*64 > wmax) continue;   // tile fully masked for this warp

        const float4* K4 = (const float4*)(smraw + buf*STAGE_BYTES);
        const float2* Vh = (const float2*)(smraw + buf*STAGE_BYTES + KSTG_BYTES);

        #pragma unroll
        for (int kk = 0; kk < 8; ++kk) {
            int cb = kt*64 + 8*kk;            // octet base column
            if (cb > wmax) break;             // remaining octets fully masked

            // ---- QK for this key octet: 3 balanced chains (3-way ILP) ----
            float scA[4] = {0.f, 0.f, 0.f, 0.f};
            float scB[4] = {0.f, 0.f, 0.f, 0.f};
            float scC[4] = {0.f, 0.f, 0.f, 0.f};
            #pragma unroll
            for (int k = 0; k < 8; ++k) {
                float4 kf = K4[(8*kk + g)*KPIT4 + k*4 + q4];
                u32 bh0 = __float_as_uint(kf.x), bh1 = __float_as_uint(kf.y);
                mma8(scA, qAhi[k], bh0, bh1);
                mma8(scB, qAlo[k], bh0, bh1);
                mma8(scC, qAhi[k],
                     __float_as_uint(kf.z), __float_as_uint(kf.w));
            }

            // ---- softmax (exp-direct) with warp-uniform fast path ----
            float p[4];
            if (cb + 7 <= wmin) {             // fully unmasked octet
                #pragma unroll
                for (int e = 0; e < 4; ++e)
                    p[e] = __expf(scA[e] + scB[e] + scC[e]);
            } else {                          // diagonal octet: element mask
                #pragma unroll
                for (int e = 0; e < 4; ++e) {
                    int r = rbase + ((e >> 1) << 3);
                    int c = cb + 2*q4 + (e & 1);
                    p[e] = (c > r) ? 0.f : __expf(scA[e] + scB[e] + scC[e]);
                }
            }
            s0 += p[0] + p[1];
            s1 += p[2] + p[3];

            // ---- relayout P acc-frag -> A-frag via quad shuffles ----
            float v00 = __shfl_sync(0xffffffffu, p[0], src0);
            float v01 = __shfl_sync(0xffffffffu, p[1], src0);
            float v20 = __shfl_sync(0xffffffffu, p[2], src0);
            float v21 = __shfl_sync(0xffffffffu, p[3], src0);
            float w00 = __shfl_sync(0xffffffffu, p[0], src1);
            float w01 = __shfl_sync(0xffffffffu, p[1], src1);
            float w20 = __shfl_sync(0xffffffffu, p[2], src1);
            float w21 = __shfl_sync(0xffffffffu, p[3], src1);
            bool odd = (q4 & 1);
            u32 pa[4];
            pa[0] = __float_as_uint(tf32hi(odd ? v01 : v00));
            pa[1] = __float_as_uint(tf32hi(odd ? v21 : v20));
            pa[2] = __float_as_uint(tf32hi(odd ? w01 : w00));
            pa[3] = __float_as_uint(tf32hi(odd ? w21 : w20));

            // ---- PV x1 (P hi x V hi) ----
            #pragma unroll
            for (int n = 0; n < 8; ++n) {
                float2 bv = Vh[(8*n + g)*VPIT2 + kk*4 + q4];
                mma8(oacc[n], pa,
                     __float_as_uint(bv.x), __float_as_uint(bv.y));
            }
        }
    }

    // ---- finalize: quad-reduce row sums, normalize, write ----
    s0 += __shfl_xor_sync(0xffffffffu, s0, 1);
    s0 += __shfl_xor_sync(0xffffffffu, s0, 2);
    s1 += __shfl_xor_sync(0xffffffffu, s1, 1);
    s1 += __shfl_xor_sync(0xffffffffu, s1, 2);
    float inv0 = 1.f / s0, inv1 = 1.f / s1;

    int b = bh >> 3, h = bh & 7;
    float* Ob0 = g_o + ((size_t)(b*NL + rbase    ))*NC + h*ND;
    float* Ob1 = g_o + ((size_t)(b*NL + rbase + 8))*NC + h*ND;
    #pragma unroll
    for (int n = 0; n < 8; ++n) {
        int d = 8*n + 2*q4;
        *(float2*)(Ob0 + d) = make_float2(oacc[n][0]*inv0, oacc[n][1]*inv0);
        *(float2*)(Ob1 + d) = make_float2(oacc[n][2]*inv1, oacc[n][3]*inv1);
    }
}

// ---------------------------------------------------------------------------
// Residual add + LayerNorm over channel, transposed-tile version (unchanged).
// ---------------------------------------------------------------------------
#define TL 16
__global__ __launch_bounds__(128)
void ln_kernel(const float* __restrict__ init, const float* __restrict__ gamma,
               const float* __restrict__ beta, float* __restrict__ y)
{
    __shared__ float xt[TL][NC + 4];

    int blk = blockIdx.x;
    int b   = blk >> 6;
    int lt  = (blk & 63) * TL;
    int tid = threadIdx.x;

    const float* ib = init + (size_t)b * NC * NL + lt;
    float*       yb = y    + (size_t)b * NC * NL + lt;

    for (int i = tid; i < NC * (TL/4); i += 128) {
        int c = i >> 2, j = i & 3;
        float4 v = *(const float4*)(ib + (size_t)c * NL + 4*j);
        xt[4*j+0][c] = v.x; xt[4*j+1][c] = v.y;
        xt[4*j+2][c] = v.z; xt[4*j+3][c] = v.w;
    }
    __syncthreads();

    int w = tid >> 5, lane = tid & 31;
    const float* ob_base = g_o + ((size_t)(b*NL + lt)) * NC;
    for (int r = w; r < TL; r += 4) {
        const float4* orow = (const float4*)(ob_base + (size_t)r * NC);
        float4 xv[4];
        float s1 = 0.f, s2 = 0.f;
        #pragma unroll
        for (int kk = 0; kk < 4; ++kk) {
            int c4 = lane + 32*kk;
            float4 ov = orow[c4];
            float4 iv = *(const float4*)(&xt[r][4*c4]);
            xv[kk] = make_float4(ov.x+iv.x, ov.y+iv.y, ov.z+iv.z, ov.w+iv.w);
            s1 += xv[kk].x + xv[kk].y + xv[kk].z + xv[kk].w;
            s2 += xv[kk].x*xv[kk].x + xv[kk].y*xv[kk].y
                + xv[kk].z*xv[kk].z + xv[kk].w*xv[kk].w;
        }
        #pragma unroll
        for (int off = 16; off; off >>= 1) {
            s1 += __shfl_xor_sync(0xffffffffu, s1, off);
            s2 += __shfl_xor_sync(0xffffffffu, s2, off);
        }
        float mu   = s1 * (1.f/512.f);
        float var  = s2 * (1.f/512.f) - mu*mu;
        float rstd = rsqrtf(var + 1e-5f);

        #pragma unroll
        for (int kk = 0; kk < 4; ++kk) {
            int c4 = lane + 32*kk;
            float4 gv = ((const float4*)gamma)[c4];
            float4 bv = ((const float4*)beta)[c4];
            float4 r4;
            r4.x = (xv[kk].x - mu)*rstd*gv.x + bv.x;
            r4.y = (xv[kk].y - mu)*rstd*gv.y + bv.y;
            r4.z = (xv[kk].z - mu)*rstd*gv.z + bv.z;
            r4.w = (xv[kk].w - mu)*rstd*gv.w + bv.w;
            *(float4*)(&xt[r][4*c4]) = r4;
        }
    }
    __syncthreads();

    for (int i = tid; i < NC * (TL/4); i += 128) {
        int c = i >> 2, j = i & 3;
        float4 v = make_float4(xt[4*j+0][c], xt[4*j+1][c],
                               xt[4*j+2][c], xt[4*j+3][c]);
        *(float4*)(yb + (size_t)c * NL + 4*j) = v;
    }
}

// ---------------------------------------------------------------------------
extern "C" void kernel_launch(void* const* d_in, const int* in_sizes, int n_in,
                              void* d_out, int out_size)
{
    const float* q     = (const float*)d_in[0];
    const float* k     = (const float*)d_in[1];
    // d_in[2] = mask — causal, handled analytically
    const float* wq    = (const float*)d_in[3];
    const float* wk    = (const float*)d_in[4];
    const float* wv    = (const float*)d_in[5];
    const float* gamma = (const float*)d_in[6];
    const float* beta  = (const float*)d_in[7];
    float* out = (float*)d_out;

    cudaFuncSetAttribute(conv_mma,
                         cudaFuncAttributeMaxDynamicSharedMemorySize, SMEM_CONV);
    cudaFuncSetAttribute(attn_kernel,
                         cudaFuncAttributeMaxDynamicSharedMemorySize, SMEM_ATTN);

    pack_w<<<dim3(64, 3), 256>>>(wq, wk, wv);
    conv_mma<<<dim3(4, 64, 3), 256, SMEM_CONV>>>(q, k);
    attn_kernel<<<dim3(8, NB*NH), 256, SMEM_ATTN>>>();
    ln_kernel<<<NB * (NL/TL), 128>>>(q, gamma, beta, out);
}

// round 16
// speedup vs baseline: 1.6495x; 1.0274x over previous
#include <cuda_runtime.h>

#define NB 8
#define NC 512
#define NL 1024
#define NH 8
#define ND 64

typedef unsigned long long u64;
typedef unsigned int u32;

// ---------------- scratch (allocation-free rule) ---------------------------
// Q/K: tf32 packed [bh][row][k(8)][q4(4)] float4 {hi(d0), hi(d0+4), lo(d0), lo(d0+4)},
// d0 = 8k + q4.
__device__ float4 g_q4[NB*NH*NL*32];
__device__ float4 g_k4[NB*NH*NL*32];
// V: tf32 hi only, [bh][d][gp(128)][j(4)] float2 {v(d, 8gp+j), v(d, 8gp+j+4)}
__device__ float2 g_v2 [NB*NH*64*512];
__device__ float  g_o  [NB*NL*NC];     // attention output, [b][l][c]
// weights pre-packed: [cv][g][t*64+c][36] f2 pairs over i {w(8k+q4), w(8k+q4+4)}
__device__ float2 g_wp_h[3*64*192*36];
__device__ float2 g_wp_l[3*64*192*36];

// ---------------- tensor helpers (legacy mma.sync on sm_103) ---------------
__device__ __forceinline__ float tf32hi(float x) {
    u32 r; asm("cvt.rna.tf32.f32 %0, %1;" : "=r"(r) : "f"(x));
    return __uint_as_float(r);
}
__device__ __forceinline__ void mma8(float d[4], const u32 a[4], u32 b0, u32 b1) {
    asm volatile("mma.sync.aligned.m16n8k8.row.col.f32.tf32.tf32.f32 "
        "{%0,%1,%2,%3}, {%4,%5,%6,%7}, {%8,%9}, {%0,%1,%2,%3};"
        : "+f"(d[0]), "+f"(d[1]), "+f"(d[2]), "+f"(d[3])
        : "r"(a[0]), "r"(a[1]), "r"(a[2]), "r"(a[3]), "r"(b0), "r"(b1));
}
__device__ __forceinline__ u32 smem_u32(const void* p) {
    u32 a; asm("{ .reg .u64 t; cvta.to.shared.u64 t, %1; cvt.u32.u64 %0, t; }"
               : "=r"(a) : "l"(p)); return a;
}

// ---------------------------------------------------------------------------
// pack_w: weights -> pair-packed tf32 hi/lo, [cv][g][t*64+c][36] f2.
// Q weights (cv=0) pre-scaled by 1/sqrt(8). grid (64, 3) x 256 threads.
// ---------------------------------------------------------------------------
__global__ void pack_w(const float* __restrict__ wq, const float* __restrict__ wk,
                       const float* __restrict__ wv)
{
    int g  = blockIdx.x;
    int cv = blockIdx.y;
    const float* w = (cv == 0) ? wq : (cv == 1) ? wk : wv;
    float s = (cv == 0) ? 0.35355339059327373f : 1.0f;

    int tid = threadIdx.x;
    #pragma unroll
    for (int it = 0; it < 24; ++it) {
        int u  = it*256 + tid;            // < 6144
        int r  = u >> 5;                  // t*64 + c
        int k4 = u & 31;
        int t  = r >> 6, c = r & 63;
        int i0 = ((k4 >> 2) << 3) | (k4 & 3);
        float v0 = w[(size_t)((g*64 + c)*64 + i0    )*3 + t] * s;
        float v1 = w[(size_t)((g*64 + c)*64 + i0 + 4)*3 + t] * s;
        float h0 = tf32hi(v0), h1 = tf32hi(v1);
        size_t base = (size_t)((cv*64 + g)*192 + r)*36 + k4;
        g_wp_h[base] = make_float2(h0, h1);
        g_wp_l[base] = make_float2(v0 - h0, v1 - h1);
    }
}

// ---------------------------------------------------------------------------
// conv_mma (R15): grouped conv1d as tensor GEMM; 2 l-tiles per block.
// cv=0(Q),1(K): x3 -> float4-packed g_q4/g_k4.  cv=2(V): x2 -> g_v2.
// grid (4 lt-pairs, 64 bg, 3 cv), 256 thr = 8 warps.
// ---------------------------------------------------------------------------
#define OFF_RAW 0                           // xs [64 i][134 f]   = 34,304 B
#define OFF_XH  34304                       // xp_hi [132][36] f2 = 38,016 B
#define OFF_XL  (OFF_XH + 38016)
#define OFF_WH  (OFF_XL + 38016)            // wp_hi [192][36] f2 = 55,296 B
#define OFF_WL  (OFF_WH + 55296)
#define SMEM_CONV (OFF_WL + 55296)          // 220,928 B

__global__ __launch_bounds__(256)
void conv_mma(const float* __restrict__ qin, const float* __restrict__ kin)
{
    extern __shared__ __align__(16) char sm[];
    u32 smb = smem_u32(sm);
    float*  xs = (float*) (sm + OFF_RAW);
    float*  oT = (float*) (sm + OFF_RAW);   // reused after GEMM
    float2* XH = (float2*)(sm + OFF_XH);
    float2* XL = (float2*)(sm + OFF_XL);
    float2* WH = (float2*)(sm + OFF_WH);
    float2* WL = (float2*)(sm + OFF_WL);

    int tid  = threadIdx.x;
    int w    = tid >> 5;
    int lane = tid & 31;
    int g    = lane >> 2;
    int q4   = lane & 3;
    int bg   = blockIdx.y;
    int cv   = blockIdx.z;
    int b    = bg >> 3, gr = bg & 7;

    const float* xg = ((cv == 0) ? qin : kin) + (size_t)(b*NC + gr*64) * NL;

    // ---- cp.async weights (once per block) ----
    {
        const char* wsh = (const char*)g_wp_h + (size_t)(cv*64 + gr)*192*288;
        const char* wsl = (const char*)g_wp_l + (size_t)(cv*64 + gr)*192*288;
        #pragma unroll
        for (int it = 0; it < 14; ++it) {
            int u = it*256 + tid;
            if (u < 3456) {
                asm volatile("cp.async.cg.shared.global [%0], [%1], 16;"
                             :: "r"(smb + OFF_WH + u*16), "l"(wsh + (size_t)u*16) : "memory");
                if (cv != 2)
                    asm volatile("cp.async.cg.shared.global [%0], [%1], 16;"
                                 :: "r"(smb + OFF_WL + u*16), "l"(wsl + (size_t)u*16) : "memory");
            }
        }
        asm volatile("cp.async.commit_group;" ::: "memory");
    }

    int base = w*16 + g;

    for (int sub = 0; sub < 2; ++sub) {
        int lt = blockIdx.x * 256 + sub * 128;
        if (sub) __syncthreads();           // prior epilogue reads of oT done

        // ---- stage raw x tile [64 i][132 r] (reflect pad), coalesced ----
        #pragma unroll
        for (int it = 0; it < 32; ++it) {
            int u = it*256 + tid;
            int i = u >> 7, r = u & 127;
            int l = lt - 1 + r;
            l = (l < 0) ? 1 : ((l >= NL) ? (2*NL - 2 - l) : l);
            xs[i*134 + r] = xg[(size_t)i*NL + l];
        }
        {   // tail rows 128..131
            int i = tid >> 2, r = 128 + (tid & 3);
            int l = lt - 1 + r;
            l = (l < 0) ? 1 : ((l >= NL) ? (2*NL - 2 - l) : l);
            xs[i*134 + r] = xg[(size_t)i*NL + l];
        }
        __syncthreads();

        // ---- transpose + tf32 split: fs = 8k + 2q + h, i = 8k + q + 4h ----
        #pragma unroll
        for (int it = 0; it < 33; ++it) {
            int u = it*256 + tid;           // < 8448 = 132*64
            int r = u >> 6, fs = u & 63;
            int k = fs >> 3, q = (fs >> 1) & 3, h = fs & 1;
            int i = 8*k + q + 4*h;
            float v = xs[i*134 + r];
            float hv = tf32hi(v);
            ((float*)XH)[r*72 + fs] = hv;
            ((float*)XL)[r*72 + fs] = v - hv;
        }
        asm volatile("cp.async.wait_group 0;" ::: "memory");
        __syncthreads();

        // ---- GEMM: warp w owns l-strip rows [w*16, +16) ----
        float oacc[8][4];
        #pragma unroll
        for (int n = 0; n < 8; ++n)
            #pragma unroll
            for (int e = 0; e < 4; ++e) oacc[n][e] = 0.f;

        #pragma unroll
        for (int t = 0; t < 3; ++t) {
            #pragma unroll
            for (int k = 0; k < 8; ++k) {
                float2 ah0 = XH[(base + t    )*36 + k*4 + q4];
                float2 ah1 = XH[(base + t + 8)*36 + k*4 + q4];
                float2 al0 = XL[(base + t    )*36 + k*4 + q4];
                float2 al1 = XL[(base + t + 8)*36 + k*4 + q4];
                u32 ahi[4] = {__float_as_uint(ah0.x), __float_as_uint(ah1.x),
                              __float_as_uint(ah0.y), __float_as_uint(ah1.y)};
                u32 alo[4] = {__float_as_uint(al0.x), __float_as_uint(al1.x),
                              __float_as_uint(al0.y), __float_as_uint(al1.y)};
                #pragma unroll
                for (int n = 0; n < 8; ++n) {
                    int ro = (t*64 + 8*n + g)*36 + k*4 + q4;
                    float2 bh = WH[ro];
                    u32 b0 = __float_as_uint(bh.x), b1 = __float_as_uint(bh.y);
                    mma8(oacc[n], ahi, b0, b1);
                    mma8(oacc[n], alo, b0, b1);
                    if (cv != 2) {
                        float2 bl = WL[ro];
                        mma8(oacc[n], ahi,
                             __float_as_uint(bl.x), __float_as_uint(bl.y));
                    }
                }
            }
        }

        // ---- store accumulators to smem oT[c][134 + l] ----
        {
            int l0 = base, l1 = base + 8;
            #pragma unroll
            for (int n = 0; n < 8; ++n) {
                int c0 = 8*n + 2*q4;
                oT[(c0    )*134 + l0] = oacc[n][0];
                oT[(c0 + 1)*134 + l0] = oacc[n][1];
                oT[(c0    )*134 + l1] = oacc[n][2];
                oT[(c0 + 1)*134 + l1] = oacc[n][3];
            }
        }
        __syncthreads();

        // ---- pack epilogue ----
        if (cv != 2) {
            float4* dst = ((cv == 0) ? g_q4 : g_k4) + (size_t)bg*NL*32;
            #pragma unroll
            for (int it = 0; it < 16; ++it) {
                int u  = it*256 + tid;      // < 4096
                int l  = u >> 5, kq = u & 31;
                int d0 = ((kq >> 2) << 3) | (kq & 3);
                float f0 = oT[(d0    )*134 + l];
                float f1 = oT[(d0 + 4)*134 + l];
                float h0 = tf32hi(f0), h1 = tf32hi(f1);
                dst[(size_t)(lt + l)*32 + kq] = make_float4(h0, h1, f0 - h0, f1 - h1);
            }
        } else {
            float2* vh = g_v2 + (size_t)bg*64*512;
            #pragma unroll
            for (int it = 0; it < 16; ++it) {
                int u  = it*256 + tid;      // < 4096
                int c  = u >> 6;
                int gp = (u >> 2) & 15, j = u & 3;
                float v0 = oT[c*134 + gp*8 + j];
                float v1 = oT[c*134 + gp*8 + j + 4];
                vh[(size_t)c*512 + ((lt >> 3) + gp)*4 + j] =
                    make_float2(tf32hi(v0), tf32hi(v1));
            }
        }
    }
}

// ---------------------------------------------------------------------------
// Causal attention R16: paired q-tiles per block (qt = 7-x then x) -> every
// block does exactly 18 key-tile units; 256 blocks = ONE uniform wave.
// Inner loop = R15 (3-chain QK x3, PV x1, mask fast-paths, 2 CTAs/SM).
// ---------------------------------------------------------------------------
#define KPIT4 36                       // float4 pitch per packed K smem row
#define KSTG_BYTES (64*KPIT4*16)       // 36,864
#define VPIT2 36
#define VSTG_BYTES (64*VPIT2*8)        // 18,432
#define STAGE_BYTES (KSTG_BYTES + VSTG_BYTES)   // 55,296
#define SMEM_ATTN (2*STAGE_BYTES)               // 110,592

__global__ __launch_bounds__(256, 2)
void attn_kernel()
{
    extern __shared__ __align__(16) char smraw[];
    u32 smb = smem_u32(smraw);

    int tid  = threadIdx.x;
    int w    = tid >> 5;
    int lane = tid & 31;
    int g    = lane >> 2;
    int q4   = lane & 3;
    int bh   = blockIdx.y;

    const float4* qp = g_q4 + (size_t)bh*NL*32;
    const char*  k4g = (const char*)(g_k4 + (size_t)bh*NL*32);
    const char*  vhg = (const char*)(g_v2 + (size_t)bh*64*512);

    int src0 = (lane & ~3) | (q4 >> 1);
    int src1 = src0 + 2;
    int rbl  = w*16 + g;

    auto stage = [&](int kt, int buf) {
        u32 base = smb + buf*STAGE_BYTES;
        #pragma unroll
        for (int i = 0; i < 12; ++i) {
            int u = i*256 + tid;                    // < 3072
            u32 dst; const char* src;
            if (u < 2048) {                         // K: 64 rows x 512B
                int r = u >> 5, c16 = u & 31;
                dst = base + r*(KPIT4*16) + c16*16;
                src = k4g + ((size_t)(kt*64 + r)*32)*16 + c16*16;
            } else {                                // V: 64 rows x 256B
                int v = u - 2048;
                int r = v >> 4, c16 = v & 15;
                dst = base + KSTG_BYTES + r*(VPIT2*8) + c16*16;
                src = vhg + ((size_t)r*512 + kt*32)*8 + c16*16;
            }
            asm volatile("cp.async.cg.shared.global [%0], [%1], 16;"
                         :: "r"(dst), "l"(src) : "memory");
        }
        asm volatile("cp.async.commit_group;" ::: "memory");
    };

    for (int half = 0; half < 2; ++half) {
        int qt   = half ? (int)blockIdx.x : (7 - (int)blockIdx.x);
        int row0 = qt * 128;

        if (half) __syncthreads();    // protect smem buffers across halves

        // ---- Q fragments for this q-tile ----
        u32 qAhi[8][4], qAlo[8][4];
        #pragma unroll
        for (int k = 0; k < 8; ++k) {
            float4 f0 = qp[(size_t)(row0+rbl  )*32 + k*4 + q4];
            float4 f1 = qp[(size_t)(row0+rbl+8)*32 + k*4 + q4];
            qAhi[k][0] = __float_as_uint(f0.x);
            qAhi[k][1] = __float_as_uint(f1.x);
            qAhi[k][2] = __float_as_uint(f0.y);
            qAhi[k][3] = __float_as_uint(f1.y);
            qAlo[k][0] = __float_as_uint(f0.z);
            qAlo[k][1] = __float_as_uint(f1.z);
            qAlo[k][2] = __float_as_uint(f0.w);
            qAlo[k][3] = __float_as_uint(f1.w);
        }

        float oacc[8][4];
        #pragma unroll
        for (int n = 0; n < 8; ++n)
            #pragma unroll
            for (int e = 0; e < 4; ++e) oacc[n][e] = 0.f;
        float s0 = 0.f, s1 = 0.f;

        int rbase = row0 + rbl;
        int wmin  = row0 + w*16;
        int wmax  = wmin + 15;
        int nkt   = 2*qt + 2;

        stage(0, 0);

        for (int kt = 0; kt < nkt; ++kt) {
            int buf = kt & 1;
            __syncthreads();
            if (kt + 1 < nkt) {
                stage(kt + 1, (kt + 1) & 1);
                asm volatile("cp.async.wait_group 1;" ::: "memory");
            } else {
                asm volatile("cp.async.wait_group 0;" ::: "memory");
            }
            __syncthreads();

            if (kt*64 > wmax) continue;   // tile fully masked for this warp

            const float4* K4 = (const float4*)(smraw + buf*STAGE_BYTES);
            const float2* Vh = (const float2*)(smraw + buf*STAGE_BYTES + KSTG_BYTES);

            #pragma unroll
            for (int kk = 0; kk < 8; ++kk) {
                int cb = kt*64 + 8*kk;            // octet base column
                if (cb > wmax) break;             // remaining octets masked

                // ---- QK: 3 balanced chains (3-way HMMA ILP) ----
                float scA[4] = {0.f, 0.f, 0.f, 0.f};
                float scB[4] = {0.f, 0.f, 0.f, 0.f};
                float scC[4] = {0.f, 0.f, 0.f, 0.f};
                #pragma unroll
                for (int k = 0; k < 8; ++k) {
                    float4 kf = K4[(8*kk + g)*KPIT4 + k*4 + q4];
                    u32 bh0 = __float_as_uint(kf.x), bh1 = __float_as_uint(kf.y);
                    mma8(scA, qAhi[k], bh0, bh1);
                    mma8(scB, qAlo[k], bh0, bh1);
                    mma8(scC, qAhi[k],
                         __float_as_uint(kf.z), __float_as_uint(kf.w));
                }

                // ---- softmax (exp-direct) with warp-uniform fast path ----
                float p[4];
                if (cb + 7 <= wmin) {             // fully unmasked octet
                    #pragma unroll
                    for (int e = 0; e < 4; ++e)
                        p[e] = __expf(scA[e] + scB[e] + scC[e]);
                } else {                          // diagonal octet
                    #pragma unroll
                    for (int e = 0; e < 4; ++e) {
                        int r = rbase + ((e >> 1) << 3);
                        int c = cb + 2*q4 + (e & 1);
                        p[e] = (c > r) ? 0.f : __expf(scA[e] + scB[e] + scC[e]);
                    }
                }
                s0 += p[0] + p[1];
                s1 += p[2] + p[3];

                // ---- relayout P acc-frag -> A-frag via quad shuffles ----
                float v00 = __shfl_sync(0xffffffffu, p[0], src0);
                float v01 = __shfl_sync(0xffffffffu, p[1], src0);
                float v20 = __shfl_sync(0xffffffffu, p[2], src0);
                float v21 = __shfl_sync(0xffffffffu, p[3], src0);
                float w00 = __shfl_sync(0xffffffffu, p[0], src1);
                float w01 = __shfl_sync(0xffffffffu, p[1], src1);
                float w20 = __shfl_sync(0xffffffffu, p[2], src1);
                float w21 = __shfl_sync(0xffffffffu, p[3], src1);
                bool odd = (q4 & 1);
                u32 pa[4];
                pa[0] = __float_as_uint(tf32hi(odd ? v01 : v00));
                pa[1] = __float_as_uint(tf32hi(odd ? v21 : v20));
                pa[2] = __float_as_uint(tf32hi(odd ? w01 : w00));
                pa[3] = __float_as_uint(tf32hi(odd ? w21 : w20));

                // ---- PV x1 (P hi x V hi) ----
                #pragma unroll
                for (int n = 0; n < 8; ++n) {
                    float2 bv = Vh[(8*n + g)*VPIT2 + kk*4 + q4];
                    mma8(oacc[n], pa,
                         __float_as_uint(bv.x), __float_as_uint(bv.y));
                }
            }
        }

        // ---- finalize this q-tile ----
        s0 += __shfl_xor_sync(0xffffffffu, s0, 1);
        s0 += __shfl_xor_sync(0xffffffffu, s0, 2);
        s1 += __shfl_xor_sync(0xffffffffu, s1, 1);
        s1 += __shfl_xor_sync(0xffffffffu, s1, 2);
        float inv0 = 1.f / s0, inv1 = 1.f / s1;

        int b = bh >> 3, h = bh & 7;
        float* Ob0 = g_o + ((size_t)(b*NL + rbase    ))*NC + h*ND;
        float* Ob1 = g_o + ((size_t)(b*NL + rbase + 8))*NC + h*ND;
        #pragma unroll
        for (int n = 0; n < 8; ++n) {
            int d = 8*n + 2*q4;
            *(float2*)(Ob0 + d) = make_float2(oacc[n][0]*inv0, oacc[n][1]*inv0);
            *(float2*)(Ob1 + d) = make_float2(oacc[n][2]*inv1, oacc[n][3]*inv1);
        }
    }
}

// ---------------------------------------------------------------------------
// Residual add + LayerNorm over channel, transposed-tile version (unchanged).
// ---------------------------------------------------------------------------
#define TL 16
__global__ __launch_bounds__(128)
void ln_kernel(const float* __restrict__ init, const float* __restrict__ gamma,
               const float* __restrict__ beta, float* __restrict__ y)
{
    __shared__ float xt[TL][NC + 4];

    int blk = blockIdx.x;
    int b   = blk >> 6;
    int lt  = (blk & 63) * TL;
    int tid = threadIdx.x;

    const float* ib = init + (size_t)b * NC * NL + lt;
    float*       yb = y    + (size_t)b * NC * NL + lt;

    for (int i = tid; i < NC * (TL/4); i += 128) {
        int c = i >> 2, j = i & 3;
        float4 v = *(const float4*)(ib + (size_t)c * NL + 4*j);
        xt[4*j+0][c] = v.x; xt[4*j+1][c] = v.y;
        xt[4*j+2][c] = v.z; xt[4*j+3][c] = v.w;
    }
    __syncthreads();

    int w = tid >> 5, lane = tid & 31;
    const float* ob_base = g_o + ((size_t)(b*NL + lt)) * NC;
    for (int r = w; r < TL; r += 4) {
        const float4* orow = (const float4*)(ob_base + (size_t)r * NC);
        float4 xv[4];
        float s1 = 0.f, s2 = 0.f;
        #pragma unroll
        for (int kk = 0; kk < 4; ++kk) {
            int c4 = lane + 32*kk;
            float4 ov = orow[c4];
            float4 iv = *(const float4*)(&xt[r][4*c4]);
            xv[kk] = make_float4(ov.x+iv.x, ov.y+iv.y, ov.z+iv.z, ov.w+iv.w);
            s1 += xv[kk].x + xv[kk].y + xv[kk].z + xv[kk].w;
            s2 += xv[kk].x*xv[kk].x + xv[kk].y*xv[kk].y
                + xv[kk].z*xv[kk].z + xv[kk].w*xv[kk].w;
        }
        #pragma unroll
        for (int off = 16; off; off >>= 1) {
            s1 += __shfl_xor_sync(0xffffffffu, s1, off);
            s2 += __shfl_xor_sync(0xffffffffu, s2, off);
        }
        float mu   = s1 * (1.f/512.f);
        float var  = s2 * (1.f/512.f) - mu*mu;
        float rstd = rsqrtf(var + 1e-5f);

        #pragma unroll
        for (int kk = 0; kk < 4; ++kk) {
            int c4 = lane + 32*kk;
            float4 gv = ((const float4*)gamma)[c4];
            float4 bv = ((const float4*)beta)[c4];
            float4 r4;
            r4.x = (xv[kk].x - mu)*rstd*gv.x + bv.x;
            r4.y = (xv[kk].y - mu)*rstd*gv.y + bv.y;
            r4.z = (xv[kk].z - mu)*rstd*gv.z + bv.z;
            r4.w = (xv[kk].w - mu)*rstd*gv.w + bv.w;
            *(float4*)(&xt[r][4*c4]) = r4;
        }
    }
    __syncthreads();

    for (int i = tid; i < NC * (TL/4); i += 128) {
        int c = i >> 2, j = i & 3;
        float4 v = make_float4(xt[4*j+0][c], xt[4*j+1][c],
                               xt[4*j+2][c], xt[4*j+3][c]);
        *(float4*)(yb + (size_t)c * NL + 4*j) = v;
    }
}

// ---------------------------------------------------------------------------
extern "C" void kernel_launch(void* const* d_in, const int* in_sizes, int n_in,
                              void* d_out, int out_size)
{
    const float* q     = (const float*)d_in[0];
    const float* k     = (const float*)d_in[1];
    // d_in[2] = mask — causal, handled analytically
    const float* wq    = (const float*)d_in[3];
    const float* wk    = (const float*)d_in[4];
    const float* wv    = (const float*)d_in[5];
    const float* gamma = (const float*)d_in[6];
    const float* beta  = (const float*)d_in[7];
    float* out = (float*)d_out;

    cudaFuncSetAttribute(conv_mma,
                         cudaFuncAttributeMaxDynamicSharedMemorySize, SMEM_CONV);
    cudaFuncSetAttribute(attn_kernel,
                         cudaFuncAttributeMaxDynamicSharedMemorySize, SMEM_ATTN);

    pack_w<<<dim3(64, 3), 256>>>(wq, wk, wv);
    conv_mma<<<dim3(4, 64, 3), 256, SMEM_CONV>>>(q, k);
    attn_kernel<<<dim3(4, NB*NH), 256, SMEM_ATTN>>>();
    ln_kernel<<<NB * (NL/TL), 128>>>(q, gamma, beta, out);
}

// round 17
// speedup vs baseline: 1.7326x; 1.0504x over previous
#include <cuda_runtime.h>

#define NB 8
#define NC 512
#define NL 1024
#define NH 8
#define ND 64

typedef unsigned long long u64;
typedef unsigned int u32;

// ---------------- scratch (allocation-free rule) ---------------------------
// Q/K: tf32 packed [bh][row][k(8)][q4(4)] float4 {hi(d0), hi(d0+4), lo(d0), lo(d0+4)},
// d0 = 8k + q4.
__device__ float4 g_q4[NB*NH*NL*32];
__device__ float4 g_k4[NB*NH*NL*32];
// V: tf32 hi only, [bh][d][gp(128)][j(4)] float2 {v(d, 8gp+j), v(d, 8gp+j+4)}
__device__ float2 g_v2 [NB*NH*64*512];
__device__ float  g_o  [NB*NL*NC];     // attention output, [b][l][c]
// weights pre-packed: [cv][g][t*64+c][36] f2 pairs over i {w(8k+q4), w(8k+q4+4)}
__device__ float2 g_wp_h[3*64*192*36];
__device__ float2 g_wp_l[3*64*192*36];

// ---------------- tensor helpers (legacy mma.sync on sm_103) ---------------
__device__ __forceinline__ float tf32hi(float x) {
    u32 r; asm("cvt.rna.tf32.f32 %0, %1;" : "=r"(r) : "f"(x));
    return __uint_as_float(r);
}
__device__ __forceinline__ void mma8(float d[4], const u32 a[4], u32 b0, u32 b1) {
    asm volatile("mma.sync.aligned.m16n8k8.row.col.f32.tf32.tf32.f32 "
        "{%0,%1,%2,%3}, {%4,%5,%6,%7}, {%8,%9}, {%0,%1,%2,%3};"
        : "+f"(d[0]), "+f"(d[1]), "+f"(d[2]), "+f"(d[3])
        : "r"(a[0]), "r"(a[1]), "r"(a[2]), "r"(a[3]), "r"(b0), "r"(b1));
}
__device__ __forceinline__ u32 smem_u32(const void* p) {
    u32 a; asm("{ .reg .u64 t; cvta.to.shared.u64 t, %1; cvt.u32.u64 %0, t; }"
               : "=r"(a) : "l"(p)); return a;
}

// ---------------------------------------------------------------------------
// pack_w: weights -> pair-packed tf32 hi/lo, [cv][g][t*64+c][36] f2.
// Q weights (cv=0) pre-scaled by 1/sqrt(8). grid (64, 3) x 256 threads.
// ---------------------------------------------------------------------------
__global__ void pack_w(const float* __restrict__ wq, const float* __restrict__ wk,
                       const float* __restrict__ wv)
{
    int g  = blockIdx.x;
    int cv = blockIdx.y;
    const float* w = (cv == 0) ? wq : (cv == 1) ? wk : wv;
    float s = (cv == 0) ? 0.35355339059327373f : 1.0f;

    int tid = threadIdx.x;
    #pragma unroll
    for (int it = 0; it < 24; ++it) {
        int u  = it*256 + tid;            // < 6144
        int r  = u >> 5;                  // t*64 + c
        int k4 = u & 31;
        int t  = r >> 6, c = r & 63;
        int i0 = ((k4 >> 2) << 3) | (k4 & 3);
        float v0 = w[(size_t)((g*64 + c)*64 + i0    )*3 + t] * s;
        float v1 = w[(size_t)((g*64 + c)*64 + i0 + 4)*3 + t] * s;
        float h0 = tf32hi(v0), h1 = tf32hi(v1);
        size_t base = (size_t)((cv*64 + g)*192 + r)*36 + k4;
        g_wp_h[base] = make_float2(h0, h1);
        g_wp_l[base] = make_float2(v0 - h0, v1 - h1);
    }
}

// ---------------------------------------------------------------------------
// conv_mma R17: fused stage+transpose — LDG -> tf32 split -> scattered STS
// straight into frag-pair layout (X pitch 37 f2 for cheap scatter).
// cv=0(Q),1(K): x3 -> float4-packed g_q4/g_k4.  cv=2(V): x2 -> g_v2.
// grid (4 lt-pairs, 64 bg, 3 cv), 256 thr = 8 warps; 2 l-tiles per block.
// ---------------------------------------------------------------------------
#define XP2 37                               // X pitch in float2 (74 floats)
#define OFF_OT  0                            // oT [64 c][134 l]   = 34,304 B
#define OFF_XH  34304                        // [132][37] f2       = 39,072 B
#define OFF_XL  (OFF_XH + 39072)
#define OFF_WH  (OFF_XL + 39072)             // [192][36] f2       = 55,296 B
#define OFF_WL  (OFF_WH + 55296)
#define SMEM_CONV (OFF_WL + 55296)           // 223,040 B

__global__ __launch_bounds__(256)
void conv_mma(const float* __restrict__ qin, const float* __restrict__ kin)
{
    extern __shared__ __align__(16) char sm[];
    u32 smb = smem_u32(sm);
    float*  oT  = (float*) (sm + OFF_OT);
    float*  XHf = (float*) (sm + OFF_XH);
    float*  XLf = (float*) (sm + OFF_XL);
    float2* XH  = (float2*)(sm + OFF_XH);
    float2* XL  = (float2*)(sm + OFF_XL);
    float2* WH  = (float2*)(sm + OFF_WH);
    float2* WL  = (float2*)(sm + OFF_WL);

    int tid  = threadIdx.x;
    int w    = tid >> 5;
    int lane = tid & 31;
    int g    = lane >> 2;
    int q4   = lane & 3;
    int bg   = blockIdx.y;
    int cv   = blockIdx.z;
    int b    = bg >> 3, gr = bg & 7;

    const float* xg = ((cv == 0) ? qin : kin) + (size_t)(b*NC + gr*64) * NL;

    // ---- cp.async weights (once per block) ----
    {
        const char* wsh = (const char*)g_wp_h + (size_t)(cv*64 + gr)*192*288;
        const char* wsl = (const char*)g_wp_l + (size_t)(cv*64 + gr)*192*288;
        #pragma unroll
        for (int it = 0; it < 14; ++it) {
            int u = it*256 + tid;
            if (u < 3456) {
                asm volatile("cp.async.cg.shared.global [%0], [%1], 16;"
                             :: "r"(smb + OFF_WH + u*16), "l"(wsh + (size_t)u*16) : "memory");
                if (cv != 2)
                    asm volatile("cp.async.cg.shared.global [%0], [%1], 16;"
                                 :: "r"(smb + OFF_WL + u*16), "l"(wsl + (size_t)u*16) : "memory");
            }
        }
        asm volatile("cp.async.commit_group;" ::: "memory");
    }

    int base = w*16 + g;

    for (int sub = 0; sub < 2; ++sub) {
        int lt = blockIdx.x * 256 + sub * 128;
        if (sub) __syncthreads();           // prior GEMM/epilogue consumers done

        // ---- fused stage+transpose: LDG -> split -> STS (64 i x 132 r) ----
        #pragma unroll
        for (int it = 0; it < 33; ++it) {
            int u = it*256 + tid;           // < 8448 = 64*132
            int i = u / 132;
            int r = u - i*132;
            int l = lt - 1 + r;
            l = (l < 0) ? 1 : ((l >= NL) ? (2*NL - 2 - l) : l);  // reflect
            float v = xg[(size_t)i*NL + l];
            // fs within row: i = 8k + q + 4h -> fs = 8k + 2q + h
            int k  = i >> 3, q = i & 3, h = (i >> 2) & 1;
            int fs = 8*k + 2*q + h;
            float hv = tf32hi(v);
            XHf[r*74 + fs] = hv;
            XLf[r*74 + fs] = v - hv;
        }
        if (sub == 0)
            asm volatile("cp.async.wait_group 0;" ::: "memory");
        __syncthreads();

        // ---- GEMM: warp w owns l-strip rows [w*16, +16) ----
        float oacc[8][4];
        #pragma unroll
        for (int n = 0; n < 8; ++n)
            #pragma unroll
            for (int e = 0; e < 4; ++e) oacc[n][e] = 0.f;

        #pragma unroll
        for (int t = 0; t < 3; ++t) {
            #pragma unroll
            for (int k = 0; k < 8; ++k) {
                float2 ah0 = XH[(base + t    )*XP2 + k*4 + q4];
                float2 ah1 = XH[(base + t + 8)*XP2 + k*4 + q4];
                float2 al0 = XL[(base + t    )*XP2 + k*4 + q4];
                float2 al1 = XL[(base + t + 8)*XP2 + k*4 + q4];
                u32 ahi[4] = {__float_as_uint(ah0.x), __float_as_uint(ah1.x),
                              __float_as_uint(ah0.y), __float_as_uint(ah1.y)};
                u32 alo[4] = {__float_as_uint(al0.x), __float_as_uint(al1.x),
                              __float_as_uint(al0.y), __float_as_uint(al1.y)};
                #pragma unroll
                for (int n = 0; n < 8; ++n) {
                    int ro = (t*64 + 8*n + g)*36 + k*4 + q4;
                    float2 bh = WH[ro];
                    u32 b0 = __float_as_uint(bh.x), b1 = __float_as_uint(bh.y);
                    mma8(oacc[n], ahi, b0, b1);
                    mma8(oacc[n], alo, b0, b1);
                    if (cv != 2) {
                        float2 bl = WL[ro];
                        mma8(oacc[n], ahi,
                             __float_as_uint(bl.x), __float_as_uint(bl.y));
                    }
                }
            }
        }

        // ---- store accumulators to smem oT[c][134 + l] ----
        {
            int l0 = base, l1 = base + 8;
            #pragma unroll
            for (int n = 0; n < 8; ++n) {
                int c0 = 8*n + 2*q4;
                oT[(c0    )*134 + l0] = oacc[n][0];
                oT[(c0 + 1)*134 + l0] = oacc[n][1];
                oT[(c0    )*134 + l1] = oacc[n][2];
                oT[(c0 + 1)*134 + l1] = oacc[n][3];
            }
        }
        __syncthreads();

        // ---- pack epilogue ----
        if (cv != 2) {
            float4* dst = ((cv == 0) ? g_q4 : g_k4) + (size_t)bg*NL*32;
            #pragma unroll
            for (int it = 0; it < 16; ++it) {
                int u  = it*256 + tid;      // < 4096
                int l  = u >> 5, kq = u & 31;
                int d0 = ((kq >> 2) << 3) | (kq & 3);
                float f0 = oT[(d0    )*134 + l];
                float f1 = oT[(d0 + 4)*134 + l];
                float h0 = tf32hi(f0), h1 = tf32hi(f1);
                dst[(size_t)(lt + l)*32 + kq] = make_float4(h0, h1, f0 - h0, f1 - h1);
            }
        } else {
            float2* vh = g_v2 + (size_t)bg*64*512;
            #pragma unroll
            for (int it = 0; it < 16; ++it) {
                int u  = it*256 + tid;      // < 4096
                int c  = u >> 6;
                int gp = (u >> 2) & 15, j = u & 3;
                float v0 = oT[c*134 + gp*8 + j];
                float v1 = oT[c*134 + gp*8 + j + 4];
                vh[(size_t)c*512 + ((lt >> 3) + gp)*4 + j] =
                    make_float2(tf32hi(v0), tf32hi(v1));
            }
        }
    }
}

// ---------------------------------------------------------------------------
// Causal attention (R16, unchanged): paired q-tiles (18 units/block, one
// uniform wave), 3-chain QK x3, PV x1, mask fast-paths, 2 CTAs/SM.
// ---------------------------------------------------------------------------
#define KPIT4 36                       // float4 pitch per packed K smem row
#define KSTG_BYTES (64*KPIT4*16)       // 36,864
#define VPIT2 36
#define VSTG_BYTES (64*VPIT2*8)        // 18,432
#define STAGE_BYTES (KSTG_BYTES + VSTG_BYTES)   // 55,296
#define SMEM_ATTN (2*STAGE_BYTES)               // 110,592

__global__ __launch_bounds__(256, 2)
void attn_kernel()
{
    extern __shared__ __align__(16) char smraw[];
    u32 smb = smem_u32(smraw);

    int tid  = threadIdx.x;
    int w    = tid >> 5;
    int lane = tid & 31;
    int g    = lane >> 2;
    int q4   = lane & 3;
    int bh   = blockIdx.y;

    const float4* qp = g_q4 + (size_t)bh*NL*32;
    const char*  k4g = (const char*)(g_k4 + (size_t)bh*NL*32);
    const char*  vhg = (const char*)(g_v2 + (size_t)bh*64*512);

    int src0 = (lane & ~3) | (q4 >> 1);
    int src1 = src0 + 2;
    int rbl  = w*16 + g;

    auto stage = [&](int kt, int buf) {
        u32 base = smb + buf*STAGE_BYTES;
        #pragma unroll
        for (int i = 0; i < 12; ++i) {
            int u = i*256 + tid;                    // < 3072
            u32 dst; const char* src;
            if (u < 2048) {                         // K: 64 rows x 512B
                int r = u >> 5, c16 = u & 31;
                dst = base + r*(KPIT4*16) + c16*16;
                src = k4g + ((size_t)(kt*64 + r)*32)*16 + c16*16;
            } else {                                // V: 64 rows x 256B
                int v = u - 2048;
                int r = v >> 4, c16 = v & 15;
                dst = base + KSTG_BYTES + r*(VPIT2*8) + c16*16;
                src = vhg + ((size_t)r*512 + kt*32)*8 + c16*16;
            }
            asm volatile("cp.async.cg.shared.global [%0], [%1], 16;"
                         :: "r"(dst), "l"(src) : "memory");
        }
        asm volatile("cp.async.commit_group;" ::: "memory");
    };

    for (int half = 0; half < 2; ++half) {
        int qt   = half ? (int)blockIdx.x : (7 - (int)blockIdx.x);
        int row0 = qt * 128;

        if (half) __syncthreads();    // protect smem buffers across halves

        u32 qAhi[8][4], qAlo[8][4];
        #pragma unroll
        for (int k = 0; k < 8; ++k) {
            float4 f0 = qp[(size_t)(row0+rbl  )*32 + k*4 + q4];
            float4 f1 = qp[(size_t)(row0+rbl+8)*32 + k*4 + q4];
            qAhi[k][0] = __float_as_uint(f0.x);
            qAhi[k][1] = __float_as_uint(f1.x);
            qAhi[k][2] = __float_as_uint(f0.y);
            qAhi[k][3] = __float_as_uint(f1.y);
            qAlo[k][0] = __float_as_uint(f0.z);
            qAlo[k][1] = __float_as_uint(f1.z);
            qAlo[k][2] = __float_as_uint(f0.w);
            qAlo[k][3] = __float_as_uint(f1.w);
        }

        float oacc[8][4];
        #pragma unroll
        for (int n = 0; n < 8; ++n)
            #pragma unroll
            for (int e = 0; e < 4; ++e) oacc[n][e] = 0.f;
        float s0 = 0.f, s1 = 0.f;

        int rbase = row0 + rbl;
        int wmin  = row0 + w*16;
        int wmax  = wmin + 15;
        int nkt   = 2*qt + 2;

        stage(0, 0);

        for (int kt = 0; kt < nkt; ++kt) {
            int buf = kt & 1;
            __syncthreads();
            if (kt + 1 < nkt) {
                stage(kt + 1, (kt + 1) & 1);
                asm volatile("cp.async.wait_group 1;" ::: "memory");
            } else {
                asm volatile("cp.async.wait_group 0;" ::: "memory");
            }
            __syncthreads();

            if (kt*64 > wmax) continue;   // tile fully masked for this warp

            const float4* K4 = (const float4*)(smraw + buf*STAGE_BYTES);
            const float2* Vh = (const float2*)(smraw + buf*STAGE_BYTES + KSTG_BYTES);

            #pragma unroll
            for (int kk = 0; kk < 8; ++kk) {
                int cb = kt*64 + 8*kk;            // octet base column
                if (cb > wmax) break;             // remaining octets masked

                float scA[4] = {0.f, 0.f, 0.f, 0.f};
                float scB[4] = {0.f, 0.f, 0.f, 0.f};
                float scC[4] = {0.f, 0.f, 0.f, 0.f};
                #pragma unroll
                for (int k = 0; k < 8; ++k) {
                    float4 kf = K4[(8*kk + g)*KPIT4 + k*4 + q4];
                    u32 bh0 = __float_as_uint(kf.x), bh1 = __float_as_uint(kf.y);
                    mma8(scA, qAhi[k], bh0, bh1);
                    mma8(scB, qAlo[k], bh0, bh1);
                    mma8(scC, qAhi[k],
                         __float_as_uint(kf.z), __float_as_uint(kf.w));
                }

                float p[4];
                if (cb + 7 <= wmin) {             // fully unmasked octet
                    #pragma unroll
                    for (int e = 0; e < 4; ++e)
                        p[e] = __expf(scA[e] + scB[e] + scC[e]);
                } else {                          // diagonal octet
                    #pragma unroll
                    for (int e = 0; e < 4; ++e) {
                        int r = rbase + ((e >> 1) << 3);
                        int c = cb + 2*q4 + (e & 1);
                        p[e] = (c > r) ? 0.f : __expf(scA[e] + scB[e] + scC[e]);
                    }
                }
                s0 += p[0] + p[1];
                s1 += p[2] + p[3];

                float v00 = __shfl_sync(0xffffffffu, p[0], src0);
                float v01 = __shfl_sync(0xffffffffu, p[1], src0);
                float v20 = __shfl_sync(0xffffffffu, p[2], src0);
                float v21 = __shfl_sync(0xffffffffu, p[3], src0);
                float w00 = __shfl_sync(0xffffffffu, p[0], src1);
                float w01 = __shfl_sync(0xffffffffu, p[1], src1);
                float w20 = __shfl_sync(0xffffffffu, p[2], src1);
                float w21 = __shfl_sync(0xffffffffu, p[3], src1);
                bool odd = (q4 & 1);
                u32 pa[4];
                pa[0] = __float_as_uint(tf32hi(odd ? v01 : v00));
                pa[1] = __float_as_uint(tf32hi(odd ? v21 : v20));
                pa[2] = __float_as_uint(tf32hi(odd ? w01 : w00));
                pa[3] = __float_as_uint(tf32hi(odd ? w21 : w20));

                #pragma unroll
                for (int n = 0; n < 8; ++n) {
                    float2 bv = Vh[(8*n + g)*VPIT2 + kk*4 + q4];
                    mma8(oacc[n], pa,
                         __float_as_uint(bv.x), __float_as_uint(bv.y));
                }
            }
        }

        s0 += __shfl_xor_sync(0xffffffffu, s0, 1);
        s0 += __shfl_xor_sync(0xffffffffu, s0, 2);
        s1 += __shfl_xor_sync(0xffffffffu, s1, 1);
        s1 += __shfl_xor_sync(0xffffffffu, s1, 2);
        float inv0 = 1.f / s0, inv1 = 1.f / s1;

        int b = bh >> 3, h = bh & 7;
        float* Ob0 = g_o + ((size_t)(b*NL + rbase    ))*NC + h*ND;
        float* Ob1 = g_o + ((size_t)(b*NL + rbase + 8))*NC + h*ND;
        #pragma unroll
        for (int n = 0; n < 8; ++n) {
            int d = 8*n + 2*q4;
            *(float2*)(Ob0 + d) = make_float2(oacc[n][0]*inv0, oacc[n][1]*inv0);
            *(float2*)(Ob1 + d) = make_float2(oacc[n][2]*inv1, oacc[n][3]*inv1);
        }
    }
}

// ---------------------------------------------------------------------------
// Residual add + LayerNorm over channel, transposed-tile version (unchanged).
// ---------------------------------------------------------------------------
#define TL 16
__global__ __launch_bounds__(128)
void ln_kernel(const float* __restrict__ init, const float* __restrict__ gamma,
               const float* __restrict__ beta, float* __restrict__ y)
{
    __shared__ float xt[TL][NC + 4];

    int blk = blockIdx.x;
    int b   = blk >> 6;
    int lt  = (blk & 63) * TL;
    int tid = threadIdx.x;

    const float* ib = init + (size_t)b * NC * NL + lt;
    float*       yb = y    + (size_t)b * NC * NL + lt;

    for (int i = tid; i < NC * (TL/4); i += 128) {
        int c = i >> 2, j = i & 3;
        float4 v = *(const float4*)(ib + (size_t)c * NL + 4*j);
        xt[4*j+0][c] = v.x; xt[4*j+1][c] = v.y;
        xt[4*j+2][c] = v.z; xt[4*j+3][c] = v.w;
    }
    __syncthreads();

    int w = tid >> 5, lane = tid & 31;
    const float* ob_base = g_o + ((size_t)(b*NL + lt)) * NC;
    for (int r = w; r < TL; r += 4) {
        const float4* orow = (const float4*)(ob_base + (size_t)r * NC);
        float4 xv[4];
        float s1 = 0.f, s2 = 0.f;
        #pragma unroll
        for (int kk = 0; kk < 4; ++kk) {
            int c4 = lane + 32*kk;
            float4 ov = orow[c4];
            float4 iv = *(const float4*)(&xt[r][4*c4]);
            xv[kk] = make_float4(ov.x+iv.x, ov.y+iv.y, ov.z+iv.z, ov.w+iv.w);
            s1 += xv[kk].x + xv[kk].y + xv[kk].z + xv[kk].w;
            s2 += xv[kk].x*xv[kk].x + xv[kk].y*xv[kk].y
                + xv[kk].z*xv[kk].z + xv[kk].w*xv[kk].w;
        }
        #pragma unroll
        for (int off = 16; off; off >>= 1) {
            s1 += __shfl_xor_sync(0xffffffffu, s1, off);
            s2 += __shfl_xor_sync(0xffffffffu, s2, off);
        }
        float mu   = s1 * (1.f/512.f);
        float var  = s2 * (1.f/512.f) - mu*mu;
        float rstd = rsqrtf(var + 1e-5f);

        #pragma unroll
        for (int kk = 0; kk < 4; ++kk) {
            int c4 = lane + 32*kk;
            float4 gv = ((const float4*)gamma)[c4];
            float4 bv = ((const float4*)beta)[c4];
            float4 r4;
            r4.x = (xv[kk].x - mu)*rstd*gv.x + bv.x;
            r4.y = (xv[kk].y - mu)*rstd*gv.y + bv.y;
            r4.z = (xv[kk].z - mu)*rstd*gv.z + bv.z;
            r4.w = (xv[kk].w - mu)*rstd*gv.w + bv.w;
            *(float4*)(&xt[r][4*c4]) = r4;
        }
    }
    __syncthreads();

    for (int i = tid; i < NC * (TL/4); i += 128) {
        int c = i >> 2, j = i & 3;
        float4 v = make_float4(xt[4*j+0][c], xt[4*j+1][c],
                               xt[4*j+2][c], xt[4*j+3][c]);
        *(float4*)(yb + (size_t)c * NL + 4*j) = v;
    }
}

// ---------------------------------------------------------------------------
extern "C" void kernel_launch(void* const* d_in, const int* in_sizes, int n_in,
                              void* d_out, int out_size)
{
    const float* q     = (const float*)d_in[0];
    const float* k     = (const float*)d_in[1];
    // d_in[2] = mask — causal, handled analytically
    const float* wq    = (const float*)d_in[3];
    const float* wk    = (const float*)d_in[4];
    const float* wv    = (const float*)d_in[5];
    const float* gamma = (const float*)d_in[6];
    const float* beta  = (const float*)d_in[7];
    float* out = (float*)d_out;

    cudaFuncSetAttribute(conv_mma,
                         cudaFuncAttributeMaxDynamicSharedMemorySize, SMEM_CONV);
    cudaFuncSetAttribute(attn_kernel,
                         cudaFuncAttributeMaxDynamicSharedMemorySize, SMEM_ATTN);

    pack_w<<<dim3(64, 3), 256>>>(wq, wk, wv);
    conv_mma<<<dim3(4, 64, 3), 256, SMEM_CONV>>>(q, k);
    attn_kernel<<<dim3(4, NB*NH), 256, SMEM_ATTN>>>();
    ln_kernel<<<NB * (NL/TL), 128>>>(q, gamma, beta, out);
}